// round 1
// baseline (speedup 1.0000x reference)
#include <cuda_runtime.h>
#include <cuda_bf16.h>
#include <math.h>

#define B_SZ 2
#define S_LEN 2048
#define D_DIM 2048
#define NH 16
#define HD 128
#define HALF_H 8
#define EPS_RMS 1e-6f
#define EPS_HN 1e-5f

// ---------------- scratch (no allocations allowed) ----------------
__device__ float g_xn[B_SZ * S_LEN * D_DIM];
__device__ float g_q [B_SZ * S_LEN * D_DIM];
__device__ float g_k [B_SZ * S_LEN * D_DIM];
__device__ float g_v [B_SZ * S_LEN * D_DIM];
__device__ float g_attn[B_SZ * S_LEN * D_DIM];
__device__ float g_ctx [B_SZ * S_LEN * D_DIM];
__device__ float g_lam[HALF_H];

// ---------------- RMSNorm ----------------
// xa = x + eps;  n = sqrt(sum((xa+eps)^2)) * sqrt(D);  out = xa/(n+eps)*g
__global__ __launch_bounds__(256) void rmsnorm_kernel(const float* __restrict__ x,
                                                      const float* __restrict__ g,
                                                      float* __restrict__ out) {
    int row = blockIdx.x;
    const float* xr = x + (size_t)row * D_DIM;
    float* orow = out + (size_t)row * D_DIM;
    float s = 0.f;
#pragma unroll
    for (int it = 0; it < D_DIM / 256; it++) {
        float v = (xr[threadIdx.x + it * 256] + EPS_RMS) + EPS_RMS;
        s = fmaf(v, v, s);
    }
#pragma unroll
    for (int off = 16; off; off >>= 1) s += __shfl_xor_sync(0xffffffffu, s, off);
    __shared__ float red[8];
    __shared__ float sinv;
    if ((threadIdx.x & 31) == 0) red[threadIdx.x >> 5] = s;
    __syncthreads();
    if (threadIdx.x == 0) {
        float t = 0.f;
#pragma unroll
        for (int i = 0; i < 8; i++) t += red[i];
        float n = sqrtf(t) * 45.254833995939045f;  // sqrt(2048)
        sinv = 1.0f / (n + EPS_RMS);
    }
    __syncthreads();
    float inv = sinv;
#pragma unroll
    for (int it = 0; it < D_DIM / 256; it++) {
        int d = threadIdx.x + it * 256;
        orow[d] = (xr[d] + EPS_RMS) * inv * g[d];
    }
}

// ---------------- SGEMM: C[M,N] = A[M,K] @ W[K,N] + bias ----------------
#define BM 128
#define BN 128
#define BK 8
#define TM 8
#define TN 8

__global__ __launch_bounds__(256) void sgemm_bias(const float* __restrict__ A,
                                                  const float* __restrict__ W,
                                                  const float* __restrict__ bias,
                                                  float* __restrict__ C,
                                                  int M, int N, int K) {
    __shared__ float As[BK][BM + 4];
    __shared__ float Bs[BK][BN + 4];
    const int tid = threadIdx.x;
    const int tRow = tid / 16, tCol = tid % 16;
    const int mBase = blockIdx.y * BM, nBase = blockIdx.x * BN;

    const int aRow = tid >> 1;          // 0..127
    const int aCol = (tid & 1) * 4;     // 0 or 4
    const int bRow = tid >> 5;          // 0..7
    const int bCol = (tid & 31) * 4;    // 0..124

    float acc[TM][TN] = {};
    float rA[TM], rB[TN];

    for (int k0 = 0; k0 < K; k0 += BK) {
        float4 a4 = *(const float4*)(A + (size_t)(mBase + aRow) * K + k0 + aCol);
        As[aCol + 0][aRow] = a4.x;
        As[aCol + 1][aRow] = a4.y;
        As[aCol + 2][aRow] = a4.z;
        As[aCol + 3][aRow] = a4.w;
        *(float4*)&Bs[bRow][bCol] = *(const float4*)(W + (size_t)(k0 + bRow) * N + nBase + bCol);
        __syncthreads();
#pragma unroll
        for (int kk = 0; kk < BK; kk++) {
            *(float4*)&rA[0] = *(const float4*)&As[kk][tRow * TM];
            *(float4*)&rA[4] = *(const float4*)&As[kk][tRow * TM + 4];
            *(float4*)&rB[0] = *(const float4*)&Bs[kk][tCol * TN];
            *(float4*)&rB[4] = *(const float4*)&Bs[kk][tCol * TN + 4];
#pragma unroll
            for (int i = 0; i < TM; i++)
#pragma unroll
                for (int j = 0; j < TN; j++) acc[i][j] = fmaf(rA[i], rB[j], acc[i][j]);
        }
        __syncthreads();
    }
#pragma unroll
    for (int i = 0; i < TM; i++) {
        int row = mBase + tRow * TM + i;
#pragma unroll
        for (int j = 0; j < TN; j += 4) {
            int col = nBase + tCol * TN + j;
            float4 o;
            o.x = acc[i][j + 0] + bias[col + 0];
            o.y = acc[i][j + 1] + bias[col + 1];
            o.z = acc[i][j + 2] + bias[col + 2];
            o.w = acc[i][j + 3] + bias[col + 3];
            *(float4*)(C + (size_t)row * N + col) = o;
        }
    }
}

// ---------------- RoPE in-place on q and k ----------------
__global__ __launch_bounds__(256) void rope_kernel(float* __restrict__ q,
                                                   float* __restrict__ k,
                                                   const int* __restrict__ positions) {
    int idx = blockIdx.x * blockDim.x + threadIdx.x;
    const int total = B_SZ * S_LEN * NH * 64;
    if (idx >= total) return;
    int j = idx & 63;
    int t = idx >> 6;
    int h = t % NH; t /= NH;
    int s = t % S_LEN;
    int b = t / S_LEN;

    // inv_freq = theta^{-(2j/128)}; fp64 trig for robust range reduction
    double e = (double)(2 * j) * (1.0 / 128.0);
    double invf = exp(-e * 13.122363377404328);  // ln(500000)
    double f = (double)positions[s] * invf;
    float c = (float)cos(f);
    float sn = (float)sin(f);

    size_t base = ((size_t)(b * S_LEN + s)) * D_DIM + (size_t)h * HD;
    float a = q[base + j], bb = q[base + 64 + j];
    q[base + j]      = a * c - bb * sn;
    q[base + 64 + j] = bb * c + a * sn;
    a = k[base + j]; bb = k[base + 64 + j];
    k[base + j]      = a * c - bb * sn;
    k[base + 64 + j] = bb * c + a * sn;
}

// ---------------- lambda per head ----------------
__global__ __launch_bounds__(256) void lam_kernel(const float* __restrict__ lq1,
                                                  const float* __restrict__ lk1,
                                                  const float* __restrict__ lq2,
                                                  const float* __restrict__ lk2,
                                                  const float* __restrict__ lam_init) {
    int h = threadIdx.x >> 5;
    int lane = threadIdx.x & 31;
    float s1 = 0.f, s2 = 0.f;
#pragma unroll
    for (int d = lane; d < HD; d += 32) {
        s1 = fmaf(lq1[h * HD + d], lk1[h * HD + d], s1);
        s2 = fmaf(lq2[h * HD + d], lk2[h * HD + d], s2);
    }
#pragma unroll
    for (int off = 16; off; off >>= 1) {
        s1 += __shfl_xor_sync(0xffffffffu, s1, off);
        s2 += __shfl_xor_sync(0xffffffffu, s2, off);
    }
    if (lane == 0 && h < HALF_H) {
        float l = expf(s1) - expf(s2) + lam_init[h];
        g_lam[h] = fminf(fmaxf(l, 0.f), 1.f);
    }
}

// ---------------- flash attention (causal, fp32) ----------------
#define FM 64
#define FN 64
#define FLASH_SMEM ((2 * 128 * 65 + 64 * 128 + 64 * 65 + 3 * 64) * 4)

__global__ __launch_bounds__(256) void flash_kernel(const float* __restrict__ Q,
                                                    const float* __restrict__ K,
                                                    const float* __restrict__ V,
                                                    float* __restrict__ O) {
    extern __shared__ float sm[];
    float* Qt = sm;                    // [128][65]  Qt[kk][m]
    float* Kt = Qt + 128 * 65;         // [128][65]  Kt[kk][n]
    float* Vs = Kt + 128 * 65;         // [64][128]
    float* Ps = Vs + 64 * 128;         // [64][65]
    float* mi = Ps + 64 * 65;          // [64]
    float* li = mi + 64;               // [64]
    float* al = li + 64;               // [64]

    const int qBase = blockIdx.x * FM;
    const int h = blockIdx.y;
    const int b = blockIdx.z;
    const int tid = threadIdx.x;
    const int ty = tid / 16, tx = tid % 16;
    const size_t headOff = (size_t)h * HD;
    const float scale = 0.088388347648318447f;  // 1/sqrt(128)

    // load Q tile transposed
    for (int s4 = tid; s4 < FM * (HD / 4); s4 += 256) {
        int row = s4 >> 5;      // s4 / 32
        int c4 = s4 & 31;
        float4 v = *(const float4*)(Q + ((size_t)(b * S_LEN + qBase + row)) * D_DIM + headOff + c4 * 4);
        Qt[(c4 * 4 + 0) * 65 + row] = v.x;
        Qt[(c4 * 4 + 1) * 65 + row] = v.y;
        Qt[(c4 * 4 + 2) * 65 + row] = v.z;
        Qt[(c4 * 4 + 3) * 65 + row] = v.w;
    }
    if (tid < FM) { mi[tid] = -1e30f; li[tid] = 0.f; }

    float Oacc[4][8];
#pragma unroll
    for (int i = 0; i < 4; i++)
#pragma unroll
        for (int dd = 0; dd < 8; dd++) Oacc[i][dd] = 0.f;

    __syncthreads();

    for (int n0 = 0; n0 <= qBase; n0 += FN) {
        // load K (transposed) and V (row-major)
        for (int s4 = tid; s4 < FN * (HD / 4); s4 += 256) {
            int row = s4 >> 5;
            int c4 = s4 & 31;
            size_t gb = ((size_t)(b * S_LEN + n0 + row)) * D_DIM + headOff + c4 * 4;
            float4 kv = *(const float4*)(K + gb);
            Kt[(c4 * 4 + 0) * 65 + row] = kv.x;
            Kt[(c4 * 4 + 1) * 65 + row] = kv.y;
            Kt[(c4 * 4 + 2) * 65 + row] = kv.z;
            Kt[(c4 * 4 + 3) * 65 + row] = kv.w;
            *(float4*)&Vs[row * HD + c4 * 4] = *(const float4*)(V + gb);
        }
        __syncthreads();

        // scores: 4x4 per thread
        float sc[4][4] = {};
#pragma unroll 4
        for (int kk = 0; kk < HD; kk++) {
            float rq[4], rk[4];
#pragma unroll
            for (int i = 0; i < 4; i++) rq[i] = Qt[kk * 65 + ty * 4 + i];
#pragma unroll
            for (int j = 0; j < 4; j++) rk[j] = Kt[kk * 65 + tx * 4 + j];
#pragma unroll
            for (int i = 0; i < 4; i++)
#pragma unroll
                for (int j = 0; j < 4; j++) sc[i][j] = fmaf(rq[i], rk[j], sc[i][j]);
        }
        bool diag = (n0 == qBase);
#pragma unroll
        for (int i = 0; i < 4; i++) {
            int m = ty * 4 + i;
#pragma unroll
            for (int j = 0; j < 4; j++) {
                int n = tx * 4 + j;
                float v = sc[i][j] * scale;
                if (diag && n > m) v = -1e30f;
                Ps[m * 65 + n] = v;
            }
        }
        __syncthreads();

        // online softmax: 4 threads per row
        {
            int r = tid >> 2;
            int part = tid & 3;
            float lm = -1e30f;
#pragma unroll
            for (int n = part * 16; n < part * 16 + 16; n++) lm = fmaxf(lm, Ps[r * 65 + n]);
            lm = fmaxf(lm, __shfl_xor_sync(0xffffffffu, lm, 1));
            lm = fmaxf(lm, __shfl_xor_sync(0xffffffffu, lm, 2));
            float oldm = mi[r];
            float newm = fmaxf(oldm, lm);
            float lsum = 0.f;
#pragma unroll
            for (int n = part * 16; n < part * 16 + 16; n++) {
                float e = __expf(Ps[r * 65 + n] - newm);
                Ps[r * 65 + n] = e;
                lsum += e;
            }
            lsum += __shfl_xor_sync(0xffffffffu, lsum, 1);
            lsum += __shfl_xor_sync(0xffffffffu, lsum, 2);
            if (part == 0) {
                float alpha = __expf(oldm - newm);
                mi[r] = newm;
                li[r] = li[r] * alpha + lsum;
                al[r] = alpha;
            }
        }
        __syncthreads();

        // rescale O and accumulate P@V
        float alr[4];
#pragma unroll
        for (int i = 0; i < 4; i++) alr[i] = al[ty * 4 + i];
#pragma unroll
        for (int i = 0; i < 4; i++)
#pragma unroll
            for (int dd = 0; dd < 8; dd++) Oacc[i][dd] *= alr[i];

        for (int n = 0; n < FN; n++) {
            float vv[8];
            *(float4*)&vv[0] = *(const float4*)&Vs[n * HD + tx * 8];
            *(float4*)&vv[4] = *(const float4*)&Vs[n * HD + tx * 8 + 4];
#pragma unroll
            for (int i = 0; i < 4; i++) {
                float p = Ps[(ty * 4 + i) * 65 + n];
#pragma unroll
                for (int dd = 0; dd < 8; dd++) Oacc[i][dd] = fmaf(p, vv[dd], Oacc[i][dd]);
            }
        }
        __syncthreads();
    }

    // epilogue: normalize and store
#pragma unroll
    for (int i = 0; i < 4; i++) {
        int m = ty * 4 + i;
        float inv = 1.0f / li[m];
        float4 o0, o1;
        o0.x = Oacc[i][0] * inv; o0.y = Oacc[i][1] * inv;
        o0.z = Oacc[i][2] * inv; o0.w = Oacc[i][3] * inv;
        o1.x = Oacc[i][4] * inv; o1.y = Oacc[i][5] * inv;
        o1.z = Oacc[i][6] * inv; o1.w = Oacc[i][7] * inv;
        size_t base = ((size_t)(b * S_LEN + qBase + m)) * D_DIM + headOff + tx * 8;
        *(float4*)(O + base) = o0;
        *(float4*)(O + base + 4) = o1;
    }
}

// ---------------- diff combine + headwise LayerNorm ----------------
__global__ __launch_bounds__(128) void combine_kernel(const float* __restrict__ attn,
                                                      const float* __restrict__ gamma,
                                                      const float* __restrict__ beta,
                                                      float* __restrict__ ctx) {
    int blk = blockIdx.x;
    int h = blk & 7;
    int row = blk >> 3;
    int d = threadIdx.x;
    size_t base = (size_t)row * D_DIM;

    float a1 = attn[base + h * HD + d];
    float a2 = attn[base + (h + 8) * HD + d];
    float o = a1 - g_lam[h] * a2;

    __shared__ float red[4];
    __shared__ float smean, svar;

    float s = o;
#pragma unroll
    for (int off = 16; off; off >>= 1) s += __shfl_xor_sync(0xffffffffu, s, off);
    if ((d & 31) == 0) red[d >> 5] = s;
    __syncthreads();
    if (d == 0) smean = (red[0] + red[1] + red[2] + red[3]) * (1.0f / 128.0f);
    __syncthreads();
    float mean = smean;
    float dv = o - mean;
    float s2 = dv * dv;
#pragma unroll
    for (int off = 16; off; off >>= 1) s2 += __shfl_xor_sync(0xffffffffu, s2, off);
    __syncthreads();
    if ((d & 31) == 0) red[d >> 5] = s2;
    __syncthreads();
    if (d == 0) svar = (red[0] + red[1] + red[2] + red[3]) * (1.0f / 128.0f);
    __syncthreads();

    float y = dv * rsqrtf(svar + EPS_HN);
    ctx[base + h * HD + d]       = gamma[h] * y + beta[h];
    ctx[base + (h + 8) * HD + d] = gamma[h + 8] * y + beta[h + 8];
}

// ---------------- launch ----------------
extern "C" void kernel_launch(void* const* d_in, const int* in_sizes, int n_in,
                              void* d_out, int out_size) {
    const float* x         = (const float*)d_in[0];
    const int*   positions = (const int*)  d_in[1];
    const float* wq        = (const float*)d_in[2];
    const float* bq        = (const float*)d_in[3];
    const float* wk        = (const float*)d_in[4];
    const float* bk        = (const float*)d_in[5];
    const float* wv        = (const float*)d_in[6];
    const float* bv        = (const float*)d_in[7];
    const float* wo        = (const float*)d_in[8];
    const float* bo        = (const float*)d_in[9];
    const float* g         = (const float*)d_in[10];
    const float* gamma     = (const float*)d_in[11];
    const float* beta      = (const float*)d_in[12];
    const float* lam_init  = (const float*)d_in[13];
    const float* lq1       = (const float*)d_in[14];
    const float* lk1       = (const float*)d_in[15];
    const float* lq2       = (const float*)d_in[16];
    const float* lk2       = (const float*)d_in[17];
    float* out = (float*)d_out;

    float *p_xn, *p_q, *p_k, *p_v, *p_attn, *p_ctx;
    cudaGetSymbolAddress((void**)&p_xn,   g_xn);
    cudaGetSymbolAddress((void**)&p_q,    g_q);
    cudaGetSymbolAddress((void**)&p_k,    g_k);
    cudaGetSymbolAddress((void**)&p_v,    g_v);
    cudaGetSymbolAddress((void**)&p_attn, g_attn);
    cudaGetSymbolAddress((void**)&p_ctx,  g_ctx);

    const int M = B_SZ * S_LEN;   // 4096
    const int N = D_DIM;          // 2048
    const int K = D_DIM;          // 2048

    rmsnorm_kernel<<<M, 256>>>(x, g, p_xn);

    dim3 gemmGrid(N / BN, M / BM);
    sgemm_bias<<<gemmGrid, 256>>>(p_xn, wq, bq, p_q, M, N, K);
    sgemm_bias<<<gemmGrid, 256>>>(p_xn, wk, bk, p_k, M, N, K);
    sgemm_bias<<<gemmGrid, 256>>>(p_xn, wv, bv, p_v, M, N, K);

    const int ropeTotal = B_SZ * S_LEN * NH * 64;
    rope_kernel<<<(ropeTotal + 255) / 256, 256>>>(p_q, p_k, positions);

    lam_kernel<<<1, 256>>>(lq1, lk1, lq2, lk2, lam_init);

    cudaFuncSetAttribute(flash_kernel, cudaFuncAttributeMaxDynamicSharedMemorySize, FLASH_SMEM);
    dim3 flashGrid(S_LEN / FM, NH, B_SZ);
    flash_kernel<<<flashGrid, 256, FLASH_SMEM>>>(p_q, p_k, p_v, p_attn);

    combine_kernel<<<M * HALF_H, 128>>>(p_attn, gamma, beta, p_ctx);

    sgemm_bias<<<gemmGrid, 256>>>(p_ctx, wo, bo, out, M, N, K);
}

// round 2
// speedup vs baseline: 1.1547x; 1.1547x over previous
#include <cuda_runtime.h>
#include <cuda_bf16.h>
#include <math.h>
#include <mma.h>

using namespace nvcuda;

#define B_SZ 2
#define S_LEN 2048
#define D_DIM 2048
#define NH 16
#define HD 128
#define HALF_H 8
#define EPS_RMS 1e-6f
#define EPS_HN 1e-5f

// ---------------- scratch (no allocations allowed) ----------------
__device__ float g_xn[B_SZ * S_LEN * D_DIM];
__device__ float g_q [B_SZ * S_LEN * D_DIM];
__device__ float g_k [B_SZ * S_LEN * D_DIM];
__device__ float g_v [B_SZ * S_LEN * D_DIM];
__device__ float g_attn[B_SZ * S_LEN * D_DIM];
__device__ float g_ctx [B_SZ * S_LEN * D_DIM];
__device__ float g_lam[HALF_H];

// ---------------- RMSNorm ----------------
__global__ __launch_bounds__(256) void rmsnorm_kernel(const float* __restrict__ x,
                                                      const float* __restrict__ g,
                                                      float* __restrict__ out) {
    int row = blockIdx.x;
    const float* xr = x + (size_t)row * D_DIM;
    float* orow = out + (size_t)row * D_DIM;
    float s = 0.f;
#pragma unroll
    for (int it = 0; it < D_DIM / 256; it++) {
        float v = (xr[threadIdx.x + it * 256] + EPS_RMS) + EPS_RMS;
        s = fmaf(v, v, s);
    }
#pragma unroll
    for (int off = 16; off; off >>= 1) s += __shfl_xor_sync(0xffffffffu, s, off);
    __shared__ float red[8];
    __shared__ float sinv;
    if ((threadIdx.x & 31) == 0) red[threadIdx.x >> 5] = s;
    __syncthreads();
    if (threadIdx.x == 0) {
        float t = 0.f;
#pragma unroll
        for (int i = 0; i < 8; i++) t += red[i];
        float n = sqrtf(t) * 45.254833995939045f;  // sqrt(2048)
        sinv = 1.0f / (n + EPS_RMS);
    }
    __syncthreads();
    float inv = sinv;
#pragma unroll
    for (int it = 0; it < D_DIM / 256; it++) {
        int d = threadIdx.x + it * 256;
        orow[d] = (xr[d] + EPS_RMS) * inv * g[d];
    }
}

// ---------------- TF32 WMMA GEMM: C[M,N] = A[M,K] @ W[K,N] + bias ----------------
#define GBM 128
#define GBN 128
#define GBK 32
#define LDA 36
#define LDB 132
#define LDC 132
// dynamic smem: max(128*36 + 32*132, 128*132) floats = 16896 floats = 67584 B
#define GEMM_SMEM (128 * 132 * 4)

__global__ __launch_bounds__(256) void gemm_tf32(const float* __restrict__ A,
                                                 const float* __restrict__ W,
                                                 const float* __restrict__ bias,
                                                 float* __restrict__ C,
                                                 int M, int N, int K) {
    extern __shared__ float sm[];
    float* As = sm;               // [128][36]
    float* Bs = sm + 128 * LDA;   // [32][132]

    const int tid = threadIdx.x;
    const int warpId = tid >> 5;
    const int wy = warpId >> 2;   // 0..1
    const int wx = warpId & 3;    // 0..3
    const int mBase = blockIdx.y * GBM;
    const int nBase = blockIdx.x * GBN;

    wmma::fragment<wmma::accumulator, 16, 16, 8, float> acc[4][2];
#pragma unroll
    for (int i = 0; i < 4; i++)
#pragma unroll
        for (int j = 0; j < 2; j++) wmma::fill_fragment(acc[i][j], 0.0f);

    for (int k0 = 0; k0 < K; k0 += GBK) {
        // stage A tile [128][32]
#pragma unroll
        for (int it = 0; it < 4; it++) {
            int idx = tid + it * 256;          // 0..1023
            int row = idx >> 3, c4 = idx & 7;
            *(float4*)&As[row * LDA + c4 * 4] =
                *(const float4*)(A + (size_t)(mBase + row) * K + k0 + c4 * 4);
        }
        // stage B tile [32][128]
#pragma unroll
        for (int it = 0; it < 4; it++) {
            int idx = tid + it * 256;
            int row = idx >> 5, c4 = idx & 31;
            *(float4*)&Bs[row * LDB + c4 * 4] =
                *(const float4*)(W + (size_t)(k0 + row) * N + nBase + c4 * 4);
        }
        __syncthreads();

#pragma unroll
        for (int kk = 0; kk < GBK; kk += 8) {
            wmma::fragment<wmma::matrix_a, 16, 16, 8, wmma::precision::tf32, wmma::row_major> af[4];
            wmma::fragment<wmma::matrix_b, 16, 16, 8, wmma::precision::tf32, wmma::row_major> bf[2];
#pragma unroll
            for (int i = 0; i < 4; i++) {
                wmma::load_matrix_sync(af[i], &As[(wy * 64 + i * 16) * LDA + kk], LDA);
#pragma unroll
                for (int e = 0; e < af[i].num_elements; e++)
                    af[i].x[e] = wmma::__float_to_tf32(af[i].x[e]);
            }
#pragma unroll
            for (int j = 0; j < 2; j++) {
                wmma::load_matrix_sync(bf[j], &Bs[kk * LDB + wx * 32 + j * 16], LDB);
#pragma unroll
                for (int e = 0; e < bf[j].num_elements; e++)
                    bf[j].x[e] = wmma::__float_to_tf32(bf[j].x[e]);
            }
#pragma unroll
            for (int i = 0; i < 4; i++)
#pragma unroll
                for (int j = 0; j < 2; j++)
                    wmma::mma_sync(acc[i][j], af[i], bf[j], acc[i][j]);
        }
        __syncthreads();
    }

    // epilogue: stage to smem (reuse), add bias, coalesced store
    float* Cs = sm;  // [128][132]
#pragma unroll
    for (int i = 0; i < 4; i++)
#pragma unroll
        for (int j = 0; j < 2; j++)
            wmma::store_matrix_sync(&Cs[(wy * 64 + i * 16) * LDC + wx * 32 + j * 16],
                                    acc[i][j], LDC, wmma::mem_row_major);
    __syncthreads();
#pragma unroll
    for (int it = 0; it < 16; it++) {
        int idx = tid + it * 256;              // 0..4095 (float4 index)
        int row = idx >> 5, c4 = idx & 31;
        float4 v = *(float4*)&Cs[row * LDC + c4 * 4];
        float4 bi = *(const float4*)(bias + nBase + c4 * 4);
        v.x += bi.x; v.y += bi.y; v.z += bi.z; v.w += bi.w;
        *(float4*)(C + (size_t)(mBase + row) * N + nBase + c4 * 4) = v;
    }
}

// ---------------- RoPE in-place on q and k ----------------
__global__ __launch_bounds__(256) void rope_kernel(float* __restrict__ q,
                                                   float* __restrict__ k,
                                                   const int* __restrict__ positions) {
    int idx = blockIdx.x * blockDim.x + threadIdx.x;
    const int total = B_SZ * S_LEN * NH * 64;
    if (idx >= total) return;
    int j = idx & 63;
    int t = idx >> 6;
    int h = t % NH; t /= NH;
    int s = t % S_LEN;
    int b = t / S_LEN;

    double e = (double)(2 * j) * (1.0 / 128.0);
    double invf = exp(-e * 13.122363377404328);  // ln(500000)
    double f = (double)positions[s] * invf;
    float c = (float)cos(f);
    float sn = (float)sin(f);

    size_t base = ((size_t)(b * S_LEN + s)) * D_DIM + (size_t)h * HD;
    float a = q[base + j], bb = q[base + 64 + j];
    q[base + j]      = a * c - bb * sn;
    q[base + 64 + j] = bb * c + a * sn;
    a = k[base + j]; bb = k[base + 64 + j];
    k[base + j]      = a * c - bb * sn;
    k[base + 64 + j] = bb * c + a * sn;
}

// ---------------- lambda per head ----------------
__global__ __launch_bounds__(256) void lam_kernel(const float* __restrict__ lq1,
                                                  const float* __restrict__ lk1,
                                                  const float* __restrict__ lq2,
                                                  const float* __restrict__ lk2,
                                                  const float* __restrict__ lam_init) {
    int h = threadIdx.x >> 5;
    int lane = threadIdx.x & 31;
    float s1 = 0.f, s2 = 0.f;
#pragma unroll
    for (int d = lane; d < HD; d += 32) {
        s1 = fmaf(lq1[h * HD + d], lk1[h * HD + d], s1);
        s2 = fmaf(lq2[h * HD + d], lk2[h * HD + d], s2);
    }
#pragma unroll
    for (int off = 16; off; off >>= 1) {
        s1 += __shfl_xor_sync(0xffffffffu, s1, off);
        s2 += __shfl_xor_sync(0xffffffffu, s2, off);
    }
    if (lane == 0 && h < HALF_H) {
        float l = expf(s1) - expf(s2) + lam_init[h];
        g_lam[h] = fminf(fmaxf(l, 0.f), 1.f);
    }
}

// ---------------- flash attention (causal, fp32) ----------------
#define FM 64
#define FN 64
#define FLASH_SMEM ((2 * 128 * 65 + 64 * 128 + 64 * 65 + 3 * 64) * 4)

__global__ __launch_bounds__(256) void flash_kernel(const float* __restrict__ Q,
                                                    const float* __restrict__ K,
                                                    const float* __restrict__ V,
                                                    float* __restrict__ O) {
    extern __shared__ float sm[];
    float* Qt = sm;                    // [128][65]  Qt[kk][m]
    float* Kt = Qt + 128 * 65;         // [128][65]  Kt[kk][n]
    float* Vs = Kt + 128 * 65;         // [64][128]
    float* Ps = Vs + 64 * 128;         // [64][65]
    float* mi = Ps + 64 * 65;          // [64]
    float* li = mi + 64;               // [64]
    float* al = li + 64;               // [64]

    const int qBase = blockIdx.x * FM;
    const int h = blockIdx.y;
    const int b = blockIdx.z;
    const int tid = threadIdx.x;
    const int ty = tid / 16, tx = tid % 16;
    const size_t headOff = (size_t)h * HD;
    const float scale = 0.088388347648318447f;  // 1/sqrt(128)

    for (int s4 = tid; s4 < FM * (HD / 4); s4 += 256) {
        int row = s4 >> 5;
        int c4 = s4 & 31;
        float4 v = *(const float4*)(Q + ((size_t)(b * S_LEN + qBase + row)) * D_DIM + headOff + c4 * 4);
        Qt[(c4 * 4 + 0) * 65 + row] = v.x;
        Qt[(c4 * 4 + 1) * 65 + row] = v.y;
        Qt[(c4 * 4 + 2) * 65 + row] = v.z;
        Qt[(c4 * 4 + 3) * 65 + row] = v.w;
    }
    if (tid < FM) { mi[tid] = -1e30f; li[tid] = 0.f; }

    float Oacc[4][8];
#pragma unroll
    for (int i = 0; i < 4; i++)
#pragma unroll
        for (int dd = 0; dd < 8; dd++) Oacc[i][dd] = 0.f;

    __syncthreads();

    for (int n0 = 0; n0 <= qBase; n0 += FN) {
        for (int s4 = tid; s4 < FN * (HD / 4); s4 += 256) {
            int row = s4 >> 5;
            int c4 = s4 & 31;
            size_t gb = ((size_t)(b * S_LEN + n0 + row)) * D_DIM + headOff + c4 * 4;
            float4 kv = *(const float4*)(K + gb);
            Kt[(c4 * 4 + 0) * 65 + row] = kv.x;
            Kt[(c4 * 4 + 1) * 65 + row] = kv.y;
            Kt[(c4 * 4 + 2) * 65 + row] = kv.z;
            Kt[(c4 * 4 + 3) * 65 + row] = kv.w;
            *(float4*)&Vs[row * HD + c4 * 4] = *(const float4*)(V + gb);
        }
        __syncthreads();

        float sc[4][4] = {};
#pragma unroll 4
        for (int kk = 0; kk < HD; kk++) {
            float rq[4], rk[4];
#pragma unroll
            for (int i = 0; i < 4; i++) rq[i] = Qt[kk * 65 + ty * 4 + i];
#pragma unroll
            for (int j = 0; j < 4; j++) rk[j] = Kt[kk * 65 + tx * 4 + j];
#pragma unroll
            for (int i = 0; i < 4; i++)
#pragma unroll
                for (int j = 0; j < 4; j++) sc[i][j] = fmaf(rq[i], rk[j], sc[i][j]);
        }
        bool diag = (n0 == qBase);
#pragma unroll
        for (int i = 0; i < 4; i++) {
            int m = ty * 4 + i;
#pragma unroll
            for (int j = 0; j < 4; j++) {
                int n = tx * 4 + j;
                float v = sc[i][j] * scale;
                if (diag && n > m) v = -1e30f;
                Ps[m * 65 + n] = v;
            }
        }
        __syncthreads();

        {
            int r = tid >> 2;
            int part = tid & 3;
            float lm = -1e30f;
#pragma unroll
            for (int n = part * 16; n < part * 16 + 16; n++) lm = fmaxf(lm, Ps[r * 65 + n]);
            lm = fmaxf(lm, __shfl_xor_sync(0xffffffffu, lm, 1));
            lm = fmaxf(lm, __shfl_xor_sync(0xffffffffu, lm, 2));
            float oldm = mi[r];
            float newm = fmaxf(oldm, lm);
            float lsum = 0.f;
#pragma unroll
            for (int n = part * 16; n < part * 16 + 16; n++) {
                float e = __expf(Ps[r * 65 + n] - newm);
                Ps[r * 65 + n] = e;
                lsum += e;
            }
            lsum += __shfl_xor_sync(0xffffffffu, lsum, 1);
            lsum += __shfl_xor_sync(0xffffffffu, lsum, 2);
            if (part == 0) {
                float alpha = __expf(oldm - newm);
                mi[r] = newm;
                li[r] = li[r] * alpha + lsum;
                al[r] = alpha;
            }
        }
        __syncthreads();

        float alr[4];
#pragma unroll
        for (int i = 0; i < 4; i++) alr[i] = al[ty * 4 + i];
#pragma unroll
        for (int i = 0; i < 4; i++)
#pragma unroll
            for (int dd = 0; dd < 8; dd++) Oacc[i][dd] *= alr[i];

        for (int n = 0; n < FN; n++) {
            float vv[8];
            *(float4*)&vv[0] = *(const float4*)&Vs[n * HD + tx * 8];
            *(float4*)&vv[4] = *(const float4*)&Vs[n * HD + tx * 8 + 4];
#pragma unroll
            for (int i = 0; i < 4; i++) {
                float p = Ps[(ty * 4 + i) * 65 + n];
#pragma unroll
                for (int dd = 0; dd < 8; dd++) Oacc[i][dd] = fmaf(p, vv[dd], Oacc[i][dd]);
            }
        }
        __syncthreads();
    }

#pragma unroll
    for (int i = 0; i < 4; i++) {
        int m = ty * 4 + i;
        float inv = 1.0f / li[m];
        float4 o0, o1;
        o0.x = Oacc[i][0] * inv; o0.y = Oacc[i][1] * inv;
        o0.z = Oacc[i][2] * inv; o0.w = Oacc[i][3] * inv;
        o1.x = Oacc[i][4] * inv; o1.y = Oacc[i][5] * inv;
        o1.z = Oacc[i][6] * inv; o1.w = Oacc[i][7] * inv;
        size_t base = ((size_t)(b * S_LEN + qBase + m)) * D_DIM + headOff + tx * 8;
        *(float4*)(O + base) = o0;
        *(float4*)(O + base + 4) = o1;
    }
}

// ---------------- diff combine + headwise LayerNorm ----------------
__global__ __launch_bounds__(128) void combine_kernel(const float* __restrict__ attn,
                                                      const float* __restrict__ gamma,
                                                      const float* __restrict__ beta,
                                                      float* __restrict__ ctx) {
    int blk = blockIdx.x;
    int h = blk & 7;
    int row = blk >> 3;
    int d = threadIdx.x;
    size_t base = (size_t)row * D_DIM;

    float a1 = attn[base + h * HD + d];
    float a2 = attn[base + (h + 8) * HD + d];
    float o = a1 - g_lam[h] * a2;

    __shared__ float red[4];
    __shared__ float smean, svar;

    float s = o;
#pragma unroll
    for (int off = 16; off; off >>= 1) s += __shfl_xor_sync(0xffffffffu, s, off);
    if ((d & 31) == 0) red[d >> 5] = s;
    __syncthreads();
    if (d == 0) smean = (red[0] + red[1] + red[2] + red[3]) * (1.0f / 128.0f);
    __syncthreads();
    float mean = smean;
    float dv = o - mean;
    float s2 = dv * dv;
#pragma unroll
    for (int off = 16; off; off >>= 1) s2 += __shfl_xor_sync(0xffffffffu, s2, off);
    __syncthreads();
    if ((d & 31) == 0) red[d >> 5] = s2;
    __syncthreads();
    if (d == 0) svar = (red[0] + red[1] + red[2] + red[3]) * (1.0f / 128.0f);
    __syncthreads();

    float y = dv * rsqrtf(svar + EPS_HN);
    ctx[base + h * HD + d]       = gamma[h] * y + beta[h];
    ctx[base + (h + 8) * HD + d] = gamma[h + 8] * y + beta[h + 8];
}

// ---------------- launch ----------------
extern "C" void kernel_launch(void* const* d_in, const int* in_sizes, int n_in,
                              void* d_out, int out_size) {
    const float* x         = (const float*)d_in[0];
    const int*   positions = (const int*)  d_in[1];
    const float* wq        = (const float*)d_in[2];
    const float* bq        = (const float*)d_in[3];
    const float* wk        = (const float*)d_in[4];
    const float* bk        = (const float*)d_in[5];
    const float* wv        = (const float*)d_in[6];
    const float* bv        = (const float*)d_in[7];
    const float* wo        = (const float*)d_in[8];
    const float* bo        = (const float*)d_in[9];
    const float* g         = (const float*)d_in[10];
    const float* gamma     = (const float*)d_in[11];
    const float* beta      = (const float*)d_in[12];
    const float* lam_init  = (const float*)d_in[13];
    const float* lq1       = (const float*)d_in[14];
    const float* lk1       = (const float*)d_in[15];
    const float* lq2       = (const float*)d_in[16];
    const float* lk2       = (const float*)d_in[17];
    float* out = (float*)d_out;

    float *p_xn, *p_q, *p_k, *p_v, *p_attn, *p_ctx;
    cudaGetSymbolAddress((void**)&p_xn,   g_xn);
    cudaGetSymbolAddress((void**)&p_q,    g_q);
    cudaGetSymbolAddress((void**)&p_k,    g_k);
    cudaGetSymbolAddress((void**)&p_v,    g_v);
    cudaGetSymbolAddress((void**)&p_attn, g_attn);
    cudaGetSymbolAddress((void**)&p_ctx,  g_ctx);

    const int M = B_SZ * S_LEN;   // 4096
    const int N = D_DIM;          // 2048
    const int K = D_DIM;          // 2048

    rmsnorm_kernel<<<M, 256>>>(x, g, p_xn);

    cudaFuncSetAttribute(gemm_tf32, cudaFuncAttributeMaxDynamicSharedMemorySize, GEMM_SMEM);
    dim3 gemmGrid(N / GBN, M / GBM);
    gemm_tf32<<<gemmGrid, 256, GEMM_SMEM>>>(p_xn, wq, bq, p_q, M, N, K);
    gemm_tf32<<<gemmGrid, 256, GEMM_SMEM>>>(p_xn, wk, bk, p_k, M, N, K);
    gemm_tf32<<<gemmGrid, 256, GEMM_SMEM>>>(p_xn, wv, bv, p_v, M, N, K);

    const int ropeTotal = B_SZ * S_LEN * NH * 64;
    rope_kernel<<<(ropeTotal + 255) / 256, 256>>>(p_q, p_k, positions);

    lam_kernel<<<1, 256>>>(lq1, lk1, lq2, lk2, lam_init);

    cudaFuncSetAttribute(flash_kernel, cudaFuncAttributeMaxDynamicSharedMemorySize, FLASH_SMEM);
    dim3 flashGrid(S_LEN / FM, NH, B_SZ);
    flash_kernel<<<flashGrid, 256, FLASH_SMEM>>>(p_q, p_k, p_v, p_attn);

    combine_kernel<<<M * HALF_H, 128>>>(p_attn, gamma, beta, p_ctx);

    gemm_tf32<<<gemmGrid, 256, GEMM_SMEM>>>(p_ctx, wo, bo, out, M, N, K);
}

// round 3
// speedup vs baseline: 1.1979x; 1.0374x over previous
#include <cuda_runtime.h>
#include <cuda_bf16.h>
#include <math.h>
#include <mma.h>

using namespace nvcuda;

#define B_SZ 2
#define S_LEN 2048
#define D_DIM 2048
#define NH 16
#define HD 128
#define HALF_H 8
#define EPS_RMS 1e-6f
#define EPS_HN 1e-5f

// ---------------- scratch (no allocations allowed) ----------------
__device__ float g_xn[B_SZ * S_LEN * D_DIM];
__device__ float g_q [B_SZ * S_LEN * D_DIM];
__device__ float g_k [B_SZ * S_LEN * D_DIM];
__device__ float g_v [B_SZ * S_LEN * D_DIM];
__device__ float g_attn[B_SZ * S_LEN * D_DIM];
__device__ float g_ctx [B_SZ * S_LEN * D_DIM];
__device__ float g_lam[HALF_H];

// ---------------- RMSNorm ----------------
__global__ __launch_bounds__(256) void rmsnorm_kernel(const float* __restrict__ x,
                                                      const float* __restrict__ g,
                                                      float* __restrict__ out) {
    int row = blockIdx.x;
    const float* xr = x + (size_t)row * D_DIM;
    float* orow = out + (size_t)row * D_DIM;
    float s = 0.f;
#pragma unroll
    for (int it = 0; it < D_DIM / 256; it++) {
        float v = (xr[threadIdx.x + it * 256] + EPS_RMS) + EPS_RMS;
        s = fmaf(v, v, s);
    }
#pragma unroll
    for (int off = 16; off; off >>= 1) s += __shfl_xor_sync(0xffffffffu, s, off);
    __shared__ float red[8];
    __shared__ float sinv;
    if ((threadIdx.x & 31) == 0) red[threadIdx.x >> 5] = s;
    __syncthreads();
    if (threadIdx.x == 0) {
        float t = 0.f;
#pragma unroll
        for (int i = 0; i < 8; i++) t += red[i];
        float n = sqrtf(t) * 45.254833995939045f;  // sqrt(2048)
        sinv = 1.0f / (n + EPS_RMS);
    }
    __syncthreads();
    float inv = sinv;
#pragma unroll
    for (int it = 0; it < D_DIM / 256; it++) {
        int d = threadIdx.x + it * 256;
        orow[d] = (xr[d] + EPS_RMS) * inv * g[d];
    }
}

// ---------------- TF32 WMMA GEMM, double-buffered ----------------
// C[M,N] = A[M,K] @ W[K,N] + bias ; blockIdx.z selects (W, bias, C)
#define GBM 128
#define GBN 128
#define GBK 32
#define LDA 36
#define LDB 132
#define LDC 132
#define A_STAGE (128 * LDA)            // 4608 floats
#define B_STAGE (32 * LDB)             // 4224 floats
#define STAGE (A_STAGE + B_STAGE)      // 8832 floats
#define GEMM_SMEM (2 * STAGE * 4)      // 70656 B (epilogue needs 128*132*4=67584 B)

__global__ __launch_bounds__(256) void gemm_tf32(const float* __restrict__ A,
                                                 const float* __restrict__ W0,
                                                 const float* __restrict__ W1,
                                                 const float* __restrict__ W2,
                                                 const float* __restrict__ b0,
                                                 const float* __restrict__ b1,
                                                 const float* __restrict__ b2,
                                                 float* __restrict__ C0,
                                                 float* __restrict__ C1,
                                                 float* __restrict__ C2,
                                                 int M, int N, int K) {
    extern __shared__ float sm[];
    const int z = blockIdx.z;
    const float* W    = (z == 0) ? W0 : (z == 1) ? W1 : W2;
    const float* bias = (z == 0) ? b0 : (z == 1) ? b1 : b2;
    float* C          = (z == 0) ? C0 : (z == 1) ? C1 : C2;

    const int tid = threadIdx.x;
    const int warpId = tid >> 5;
    const int wy = warpId >> 2;   // 0..1
    const int wx = warpId & 3;    // 0..3
    const int mBase = blockIdx.y * GBM;
    const int nBase = blockIdx.x * GBN;

    // staging index precompute
    const int aRow = tid >> 1;            // 0..127 (row per 2 threads, 2 f4 each pass? no:)
    // A tile: 128 rows x 32 cols = 1024 float4; idx = tid + it*256; row=idx>>3, c4=idx&7
    // B tile: 32 rows x 128 cols = 1024 float4; row=idx>>5, c4=idx&31
    (void)aRow;

    wmma::fragment<wmma::accumulator, 16, 16, 8, float> acc[4][2];
#pragma unroll
    for (int i = 0; i < 4; i++)
#pragma unroll
        for (int j = 0; j < 2; j++) wmma::fill_fragment(acc[i][j], 0.0f);

    float4 ra[4], rb[4];

    // prologue: load tile 0
#pragma unroll
    for (int it = 0; it < 4; it++) {
        int idx = tid + it * 256;
        ra[it] = *(const float4*)(A + (size_t)(mBase + (idx >> 3)) * K + (idx & 7) * 4);
        rb[it] = *(const float4*)(W + (size_t)(idx >> 5) * N + nBase + (idx & 31) * 4);
    }
    // stage into buf0 with tf32 conversion
#pragma unroll
    for (int it = 0; it < 4; it++) {
        int idx = tid + it * 256;
        float4 a = ra[it];
        a.x = wmma::__float_to_tf32(a.x); a.y = wmma::__float_to_tf32(a.y);
        a.z = wmma::__float_to_tf32(a.z); a.w = wmma::__float_to_tf32(a.w);
        *(float4*)&sm[(idx >> 3) * LDA + (idx & 7) * 4] = a;
        float4 b = rb[it];
        b.x = wmma::__float_to_tf32(b.x); b.y = wmma::__float_to_tf32(b.y);
        b.z = wmma::__float_to_tf32(b.z); b.w = wmma::__float_to_tf32(b.w);
        *(float4*)&sm[A_STAGE + (idx >> 5) * LDB + (idx & 31) * 4] = b;
    }
    __syncthreads();

    int phase = 0;
    for (int k0 = 0; k0 < K; k0 += GBK, phase ^= 1) {
        const bool more = (k0 + GBK) < K;
        // prefetch next tile into registers (latency hidden by compute below)
        if (more) {
#pragma unroll
            for (int it = 0; it < 4; it++) {
                int idx = tid + it * 256;
                ra[it] = *(const float4*)(A + (size_t)(mBase + (idx >> 3)) * K + k0 + GBK + (idx & 7) * 4);
                rb[it] = *(const float4*)(W + (size_t)(k0 + GBK + (idx >> 5)) * N + nBase + (idx & 31) * 4);
            }
        }

        const float* Abuf = sm + phase * STAGE;
        const float* Bbuf = Abuf + A_STAGE;
#pragma unroll
        for (int kk = 0; kk < GBK; kk += 8) {
            wmma::fragment<wmma::matrix_a, 16, 16, 8, wmma::precision::tf32, wmma::row_major> af[4];
            wmma::fragment<wmma::matrix_b, 16, 16, 8, wmma::precision::tf32, wmma::row_major> bf[2];
#pragma unroll
            for (int i = 0; i < 4; i++)
                wmma::load_matrix_sync(af[i], &Abuf[(wy * 64 + i * 16) * LDA + kk], LDA);
#pragma unroll
            for (int j = 0; j < 2; j++)
                wmma::load_matrix_sync(bf[j], &Bbuf[kk * LDB + wx * 32 + j * 16], LDB);
#pragma unroll
            for (int i = 0; i < 4; i++)
#pragma unroll
                for (int j = 0; j < 2; j++)
                    wmma::mma_sync(acc[i][j], af[i], bf[j], acc[i][j]);
        }

        if (more) {
            float* Adst = sm + (phase ^ 1) * STAGE;
            float* Bdst = Adst + A_STAGE;
#pragma unroll
            for (int it = 0; it < 4; it++) {
                int idx = tid + it * 256;
                float4 a = ra[it];
                a.x = wmma::__float_to_tf32(a.x); a.y = wmma::__float_to_tf32(a.y);
                a.z = wmma::__float_to_tf32(a.z); a.w = wmma::__float_to_tf32(a.w);
                *(float4*)&Adst[(idx >> 3) * LDA + (idx & 7) * 4] = a;
                float4 b = rb[it];
                b.x = wmma::__float_to_tf32(b.x); b.y = wmma::__float_to_tf32(b.y);
                b.z = wmma::__float_to_tf32(b.z); b.w = wmma::__float_to_tf32(b.w);
                *(float4*)&Bdst[A_STAGE + 0 + (idx >> 5) * LDB + (idx & 31) * 4 - A_STAGE] = b;
                (void)Bdst;
            }
        }
        __syncthreads();
    }

    // epilogue: stage to smem (reuse), add bias, coalesced store
    float* Cs = sm;  // [128][132]
#pragma unroll
    for (int i = 0; i < 4; i++)
#pragma unroll
        for (int j = 0; j < 2; j++)
            wmma::store_matrix_sync(&Cs[(wy * 64 + i * 16) * LDC + wx * 32 + j * 16],
                                    acc[i][j], LDC, wmma::mem_row_major);
    __syncthreads();
#pragma unroll
    for (int it = 0; it < 16; it++) {
        int idx = tid + it * 256;              // float4 index
        int row = idx >> 5, c4 = idx & 31;
        float4 v = *(float4*)&Cs[row * LDC + c4 * 4];
        float4 bi = *(const float4*)(bias + nBase + c4 * 4);
        v.x += bi.x; v.y += bi.y; v.z += bi.z; v.w += bi.w;
        *(float4*)(C + (size_t)(mBase + row) * N + nBase + c4 * 4) = v;
    }
}

// ---------------- RoPE in-place on q and k ----------------
__global__ __launch_bounds__(256) void rope_kernel(float* __restrict__ q,
                                                   float* __restrict__ k,
                                                   const int* __restrict__ positions) {
    int idx = blockIdx.x * blockDim.x + threadIdx.x;
    const int total = B_SZ * S_LEN * NH * 64;
    if (idx >= total) return;
    int j = idx & 63;
    int t = idx >> 6;
    int h = t % NH; t /= NH;
    int s = t % S_LEN;
    int b = t / S_LEN;

    double e = (double)(2 * j) * (1.0 / 128.0);
    double invf = exp(-e * 13.122363377404328);  // ln(500000)
    double f = (double)positions[s] * invf;
    float c = (float)cos(f);
    float sn = (float)sin(f);

    size_t base = ((size_t)(b * S_LEN + s)) * D_DIM + (size_t)h * HD;
    float a = q[base + j], bb = q[base + 64 + j];
    q[base + j]      = a * c - bb * sn;
    q[base + 64 + j] = bb * c + a * sn;
    a = k[base + j]; bb = k[base + 64 + j];
    k[base + j]      = a * c - bb * sn;
    k[base + 64 + j] = bb * c + a * sn;
}

// ---------------- lambda per head ----------------
__global__ __launch_bounds__(256) void lam_kernel(const float* __restrict__ lq1,
                                                  const float* __restrict__ lk1,
                                                  const float* __restrict__ lq2,
                                                  const float* __restrict__ lk2,
                                                  const float* __restrict__ lam_init) {
    int h = threadIdx.x >> 5;
    int lane = threadIdx.x & 31;
    float s1 = 0.f, s2 = 0.f;
#pragma unroll
    for (int d = lane; d < HD; d += 32) {
        s1 = fmaf(lq1[h * HD + d], lk1[h * HD + d], s1);
        s2 = fmaf(lq2[h * HD + d], lk2[h * HD + d], s2);
    }
#pragma unroll
    for (int off = 16; off; off >>= 1) {
        s1 += __shfl_xor_sync(0xffffffffu, s1, off);
        s2 += __shfl_xor_sync(0xffffffffu, s2, off);
    }
    if (lane == 0 && h < HALF_H) {
        float l = expf(s1) - expf(s2) + lam_init[h];
        g_lam[h] = fminf(fmaxf(l, 0.f), 1.f);
    }
}

// ---------------- flash attention (causal, fp32) ----------------
#define FM 64
#define FN 64
#define FLASH_SMEM ((2 * 128 * 65 + 64 * 128 + 64 * 65 + 3 * 64) * 4)

__global__ __launch_bounds__(256) void flash_kernel(const float* __restrict__ Q,
                                                    const float* __restrict__ K,
                                                    const float* __restrict__ V,
                                                    float* __restrict__ O) {
    extern __shared__ float sm[];
    float* Qt = sm;                    // [128][65]  Qt[kk][m]
    float* Kt = Qt + 128 * 65;         // [128][65]  Kt[kk][n]
    float* Vs = Kt + 128 * 65;         // [64][128]
    float* Ps = Vs + 64 * 128;         // [64][65]
    float* mi = Ps + 64 * 65;          // [64]
    float* li = mi + 64;               // [64]
    float* al = li + 64;               // [64]

    const int qBase = blockIdx.x * FM;
    const int h = blockIdx.y;
    const int b = blockIdx.z;
    const int tid = threadIdx.x;
    const int ty = tid / 16, tx = tid % 16;
    const size_t headOff = (size_t)h * HD;
    const float scale = 0.088388347648318447f;  // 1/sqrt(128)

    for (int s4 = tid; s4 < FM * (HD / 4); s4 += 256) {
        int row = s4 >> 5;
        int c4 = s4 & 31;
        float4 v = *(const float4*)(Q + ((size_t)(b * S_LEN + qBase + row)) * D_DIM + headOff + c4 * 4);
        Qt[(c4 * 4 + 0) * 65 + row] = v.x;
        Qt[(c4 * 4 + 1) * 65 + row] = v.y;
        Qt[(c4 * 4 + 2) * 65 + row] = v.z;
        Qt[(c4 * 4 + 3) * 65 + row] = v.w;
    }
    if (tid < FM) { mi[tid] = -1e30f; li[tid] = 0.f; }

    float Oacc[4][8];
#pragma unroll
    for (int i = 0; i < 4; i++)
#pragma unroll
        for (int dd = 0; dd < 8; dd++) Oacc[i][dd] = 0.f;

    __syncthreads();

    for (int n0 = 0; n0 <= qBase; n0 += FN) {
        for (int s4 = tid; s4 < FN * (HD / 4); s4 += 256) {
            int row = s4 >> 5;
            int c4 = s4 & 31;
            size_t gb = ((size_t)(b * S_LEN + n0 + row)) * D_DIM + headOff + c4 * 4;
            float4 kv = *(const float4*)(K + gb);
            Kt[(c4 * 4 + 0) * 65 + row] = kv.x;
            Kt[(c4 * 4 + 1) * 65 + row] = kv.y;
            Kt[(c4 * 4 + 2) * 65 + row] = kv.z;
            Kt[(c4 * 4 + 3) * 65 + row] = kv.w;
            *(float4*)&Vs[row * HD + c4 * 4] = *(const float4*)(V + gb);
        }
        __syncthreads();

        float sc[4][4] = {};
#pragma unroll 4
        for (int kk = 0; kk < HD; kk++) {
            float rq[4], rk[4];
#pragma unroll
            for (int i = 0; i < 4; i++) rq[i] = Qt[kk * 65 + ty * 4 + i];
#pragma unroll
            for (int j = 0; j < 4; j++) rk[j] = Kt[kk * 65 + tx * 4 + j];
#pragma unroll
            for (int i = 0; i < 4; i++)
#pragma unroll
                for (int j = 0; j < 4; j++) sc[i][j] = fmaf(rq[i], rk[j], sc[i][j]);
        }
        bool diag = (n0 == qBase);
#pragma unroll
        for (int i = 0; i < 4; i++) {
            int m = ty * 4 + i;
#pragma unroll
            for (int j = 0; j < 4; j++) {
                int n = tx * 4 + j;
                float v = sc[i][j] * scale;
                if (diag && n > m) v = -1e30f;
                Ps[m * 65 + n] = v;
            }
        }
        __syncthreads();

        {
            int r = tid >> 2;
            int part = tid & 3;
            float lm = -1e30f;
#pragma unroll
            for (int n = part * 16; n < part * 16 + 16; n++) lm = fmaxf(lm, Ps[r * 65 + n]);
            lm = fmaxf(lm, __shfl_xor_sync(0xffffffffu, lm, 1));
            lm = fmaxf(lm, __shfl_xor_sync(0xffffffffu, lm, 2));
            float oldm = mi[r];
            float newm = fmaxf(oldm, lm);
            float lsum = 0.f;
#pragma unroll
            for (int n = part * 16; n < part * 16 + 16; n++) {
                float e = __expf(Ps[r * 65 + n] - newm);
                Ps[r * 65 + n] = e;
                lsum += e;
            }
            lsum += __shfl_xor_sync(0xffffffffu, lsum, 1);
            lsum += __shfl_xor_sync(0xffffffffu, lsum, 2);
            if (part == 0) {
                float alpha = __expf(oldm - newm);
                mi[r] = newm;
                li[r] = li[r] * alpha + lsum;
                al[r] = alpha;
            }
        }
        __syncthreads();

        float alr[4];
#pragma unroll
        for (int i = 0; i < 4; i++) alr[i] = al[ty * 4 + i];
#pragma unroll
        for (int i = 0; i < 4; i++)
#pragma unroll
            for (int dd = 0; dd < 8; dd++) Oacc[i][dd] *= alr[i];

        for (int n = 0; n < FN; n++) {
            float vv[8];
            *(float4*)&vv[0] = *(const float4*)&Vs[n * HD + tx * 8];
            *(float4*)&vv[4] = *(const float4*)&Vs[n * HD + tx * 8 + 4];
#pragma unroll
            for (int i = 0; i < 4; i++) {
                float p = Ps[(ty * 4 + i) * 65 + n];
#pragma unroll
                for (int dd = 0; dd < 8; dd++) Oacc[i][dd] = fmaf(p, vv[dd], Oacc[i][dd]);
            }
        }
        __syncthreads();
    }

#pragma unroll
    for (int i = 0; i < 4; i++) {
        int m = ty * 4 + i;
        float inv = 1.0f / li[m];
        float4 o0, o1;
        o0.x = Oacc[i][0] * inv; o0.y = Oacc[i][1] * inv;
        o0.z = Oacc[i][2] * inv; o0.w = Oacc[i][3] * inv;
        o1.x = Oacc[i][4] * inv; o1.y = Oacc[i][5] * inv;
        o1.z = Oacc[i][6] * inv; o1.w = Oacc[i][7] * inv;
        size_t base = ((size_t)(b * S_LEN + qBase + m)) * D_DIM + headOff + tx * 8;
        *(float4*)(O + base) = o0;
        *(float4*)(O + base + 4) = o1;
    }
}

// ---------------- diff combine + headwise LayerNorm ----------------
__global__ __launch_bounds__(128) void combine_kernel(const float* __restrict__ attn,
                                                      const float* __restrict__ gamma,
                                                      const float* __restrict__ beta,
                                                      float* __restrict__ ctx) {
    int blk = blockIdx.x;
    int h = blk & 7;
    int row = blk >> 3;
    int d = threadIdx.x;
    size_t base = (size_t)row * D_DIM;

    float a1 = attn[base + h * HD + d];
    float a2 = attn[base + (h + 8) * HD + d];
    float o = a1 - g_lam[h] * a2;

    __shared__ float red[4];
    __shared__ float smean, svar;

    float s = o;
#pragma unroll
    for (int off = 16; off; off >>= 1) s += __shfl_xor_sync(0xffffffffu, s, off);
    if ((d & 31) == 0) red[d >> 5] = s;
    __syncthreads();
    if (d == 0) smean = (red[0] + red[1] + red[2] + red[3]) * (1.0f / 128.0f);
    __syncthreads();
    float mean = smean;
    float dv = o - mean;
    float s2 = dv * dv;
#pragma unroll
    for (int off = 16; off; off >>= 1) s2 += __shfl_xor_sync(0xffffffffu, s2, off);
    __syncthreads();
    if ((d & 31) == 0) red[d >> 5] = s2;
    __syncthreads();
    if (d == 0) svar = (red[0] + red[1] + red[2] + red[3]) * (1.0f / 128.0f);
    __syncthreads();

    float y = dv * rsqrtf(svar + EPS_HN);
    ctx[base + h * HD + d]       = gamma[h] * y + beta[h];
    ctx[base + (h + 8) * HD + d] = gamma[h + 8] * y + beta[h + 8];
}

// ---------------- launch ----------------
extern "C" void kernel_launch(void* const* d_in, const int* in_sizes, int n_in,
                              void* d_out, int out_size) {
    const float* x         = (const float*)d_in[0];
    const int*   positions = (const int*)  d_in[1];
    const float* wq        = (const float*)d_in[2];
    const float* bq        = (const float*)d_in[3];
    const float* wk        = (const float*)d_in[4];
    const float* bk        = (const float*)d_in[5];
    const float* wv        = (const float*)d_in[6];
    const float* bv        = (const float*)d_in[7];
    const float* wo        = (const float*)d_in[8];
    const float* bo        = (const float*)d_in[9];
    const float* g         = (const float*)d_in[10];
    const float* gamma     = (const float*)d_in[11];
    const float* beta      = (const float*)d_in[12];
    const float* lam_init  = (const float*)d_in[13];
    const float* lq1       = (const float*)d_in[14];
    const float* lk1       = (const float*)d_in[15];
    const float* lq2       = (const float*)d_in[16];
    const float* lk2       = (const float*)d_in[17];
    float* out = (float*)d_out;

    float *p_xn, *p_q, *p_k, *p_v, *p_attn, *p_ctx;
    cudaGetSymbolAddress((void**)&p_xn,   g_xn);
    cudaGetSymbolAddress((void**)&p_q,    g_q);
    cudaGetSymbolAddress((void**)&p_k,    g_k);
    cudaGetSymbolAddress((void**)&p_v,    g_v);
    cudaGetSymbolAddress((void**)&p_attn, g_attn);
    cudaGetSymbolAddress((void**)&p_ctx,  g_ctx);

    const int M = B_SZ * S_LEN;   // 4096
    const int N = D_DIM;          // 2048
    const int K = D_DIM;          // 2048

    rmsnorm_kernel<<<M, 256>>>(x, g, p_xn);

    cudaFuncSetAttribute(gemm_tf32, cudaFuncAttributeMaxDynamicSharedMemorySize, GEMM_SMEM);
    // fused Q,K,V projections: blockIdx.z selects the weight/output
    dim3 qkvGrid(N / GBN, M / GBM, 3);
    gemm_tf32<<<qkvGrid, 256, GEMM_SMEM>>>(p_xn, wq, wk, wv, bq, bk, bv,
                                           p_q, p_k, p_v, M, N, K);

    const int ropeTotal = B_SZ * S_LEN * NH * 64;
    rope_kernel<<<(ropeTotal + 255) / 256, 256>>>(p_q, p_k, positions);

    lam_kernel<<<1, 256>>>(lq1, lk1, lq2, lk2, lam_init);

    cudaFuncSetAttribute(flash_kernel, cudaFuncAttributeMaxDynamicSharedMemorySize, FLASH_SMEM);
    dim3 flashGrid(S_LEN / FM, NH, B_SZ);
    flash_kernel<<<flashGrid, 256, FLASH_SMEM>>>(p_q, p_k, p_v, p_attn);

    combine_kernel<<<M * HALF_H, 128>>>(p_attn, gamma, beta, p_ctx);

    dim3 oGrid(N / GBN, M / GBM, 1);
    gemm_tf32<<<oGrid, 256, GEMM_SMEM>>>(p_ctx, wo, wo, wo, bo, bo, bo,
                                         out, out, out, M, N, K);
}

// round 5
// speedup vs baseline: 1.3999x; 1.1686x over previous
#include <cuda_runtime.h>
#include <cuda_bf16.h>
#include <math.h>
#include <mma.h>
#include <cstdint>

using namespace nvcuda;

#define B_SZ 2
#define S_LEN 2048
#define D_DIM 2048
#define NH 16
#define HD 128
#define HALF_H 8
#define EPS_RMS 1e-6f
#define EPS_HN 1e-5f

// ---------------- scratch (no allocations allowed) ----------------
__device__ float g_xn[B_SZ * S_LEN * D_DIM];
__device__ float g_q [B_SZ * S_LEN * D_DIM];
__device__ float g_k [B_SZ * S_LEN * D_DIM];
__device__ float g_v [B_SZ * S_LEN * D_DIM];
__device__ float g_attn[B_SZ * S_LEN * D_DIM];
__device__ float g_ctx [B_SZ * S_LEN * D_DIM];
__device__ float g_wr  [4 * D_DIM * D_DIM];   // tf32-rounded weights [K,N], 4 slices
__device__ float g_lam[HALF_H];

// ---------------- cp.async helpers ----------------
__device__ __forceinline__ uint32_t smem_u32(const void* p) {
    uint32_t a;
    asm("{ .reg .u64 t; cvta.to.shared.u64 t, %1; cvt.u32.u64 %0, t; }" : "=r"(a) : "l"(p));
    return a;
}
__device__ __forceinline__ void cp_async16(uint32_t dst, const void* src) {
    asm volatile("cp.async.cg.shared.global [%0], [%1], 16;" :: "r"(dst), "l"(src));
}
__device__ __forceinline__ void cp_commit() {
    asm volatile("cp.async.commit_group;");
}
template<int N> __device__ __forceinline__ void cp_wait() {
    asm volatile("cp.async.wait_group %0;" :: "n"(N));
}

// ---------------- tf32 rounding of weights ----------------
__global__ __launch_bounds__(256) void round_w_kernel(const float* __restrict__ w0,
                                                      const float* __restrict__ w1,
                                                      const float* __restrict__ w2,
                                                      const float* __restrict__ w3,
                                                      float* __restrict__ dst) {
    const int z = blockIdx.y;
    const float* src = (z == 0) ? w0 : (z == 1) ? w1 : (z == 2) ? w2 : w3;
    float* d = dst + (size_t)z * D_DIM * D_DIM;
    int i4 = blockIdx.x * 256 + threadIdx.x;           // float4 index
    float4 v = *(const float4*)(src + (size_t)i4 * 4);
    v.x = wmma::__float_to_tf32(v.x); v.y = wmma::__float_to_tf32(v.y);
    v.z = wmma::__float_to_tf32(v.z); v.w = wmma::__float_to_tf32(v.w);
    *(float4*)(d + (size_t)i4 * 4) = v;
}

// ---------------- RMSNorm (emits tf32-rounded output) ----------------
__global__ __launch_bounds__(256) void rmsnorm_kernel(const float* __restrict__ x,
                                                      const float* __restrict__ g,
                                                      float* __restrict__ out) {
    int row = blockIdx.x;
    const float* xr = x + (size_t)row * D_DIM;
    float* orow = out + (size_t)row * D_DIM;
    float s = 0.f;
#pragma unroll
    for (int it = 0; it < D_DIM / 256; it++) {
        float v = (xr[threadIdx.x + it * 256] + EPS_RMS) + EPS_RMS;
        s = fmaf(v, v, s);
    }
#pragma unroll
    for (int off = 16; off; off >>= 1) s += __shfl_xor_sync(0xffffffffu, s, off);
    __shared__ float red[8];
    __shared__ float sinv;
    if ((threadIdx.x & 31) == 0) red[threadIdx.x >> 5] = s;
    __syncthreads();
    if (threadIdx.x == 0) {
        float t = 0.f;
#pragma unroll
        for (int i = 0; i < 8; i++) t += red[i];
        float n = sqrtf(t) * 45.254833995939045f;  // sqrt(2048)
        sinv = 1.0f / (n + EPS_RMS);
    }
    __syncthreads();
    float inv = sinv;
#pragma unroll
    for (int it = 0; it < D_DIM / 256; it++) {
        int d = threadIdx.x + it * 256;
        orow[d] = wmma::__float_to_tf32((xr[d] + EPS_RMS) * inv * g[d]);
    }
}

// ---------------- TF32 WMMA GEMM, cp.async 3-stage pipeline ----------------
// C[M,N] = A[M,K] @ W[K,N] + bias.  A and W are pre-rounded to tf32 values.
// CTA tile 128x256, 8 warps of 64x64. BK=32.
#define CTA_M 128
#define CTA_N 256
#define GBK 32
#define LDA 36
#define LDB 260
#define LDC 132
#define STAGE_A (CTA_M * LDA)                 // 4608 floats
#define STAGE_B (GBK * LDB)                   // 8320 floats
#define STAGE_FL (STAGE_A + STAGE_B)          // 12928 floats
#define NSTAGE 3
#define GEMM_SMEM (NSTAGE * STAGE_FL * 4)     // 155136 B
#define NKT (D_DIM / GBK)                     // 64

__global__ __launch_bounds__(256) void gemm_tf32(const float* __restrict__ A,
                                                 const float* __restrict__ Wbase,
                                                 int zoff,
                                                 const float* __restrict__ b0,
                                                 const float* __restrict__ b1,
                                                 const float* __restrict__ b2,
                                                 float* __restrict__ C0,
                                                 float* __restrict__ C1,
                                                 float* __restrict__ C2) {
    extern __shared__ float sm[];
    const uint32_t smem_base = smem_u32(sm);
    const int z = blockIdx.z;
    const float* W    = Wbase + (size_t)(z + zoff) * D_DIM * D_DIM;
    const float* bias = (z == 0) ? b0 : (z == 1) ? b1 : b2;
    float* C          = (z == 0) ? C0 : (z == 1) ? C1 : C2;

    const int tid = threadIdx.x;
    const int warpId = tid >> 5;
    const int wy = warpId >> 2;     // 0..1 -> m block of 64
    const int wx = warpId & 3;      // 0..3 -> n block of 64
    const int mBase = blockIdx.y * CTA_M;
    const int nBase = blockIdx.x * CTA_N;

    wmma::fragment<wmma::accumulator, 16, 16, 8, float> acc[4][4];
#pragma unroll
    for (int i = 0; i < 4; i++)
#pragma unroll
        for (int j = 0; j < 4; j++) wmma::fill_fragment(acc[i][j], 0.0f);

    auto stage = [&](int buf, int k0) {
        uint32_t sa = smem_base + (uint32_t)(buf * STAGE_FL * 4);
        uint32_t sb = sa + STAGE_A * 4;
        // A tile: 128 rows x 8 f4-chunks
#pragma unroll
        for (int it = 0; it < 4; it++) {
            int idx = tid + it * 256;
            int row = idx >> 3, c = idx & 7;
            cp_async16(sa + (uint32_t)(row * LDA + c * 4) * 4,
                       A + (size_t)(mBase + row) * D_DIM + k0 + c * 4);
        }
        // B tile: 32 rows x 64 f4-chunks
#pragma unroll
        for (int it = 0; it < 8; it++) {
            int idx = tid + it * 256;
            int row = idx >> 6, c = idx & 63;
            cp_async16(sb + (uint32_t)(row * LDB + c * 4) * 4,
                       W + (size_t)(k0 + row) * D_DIM + nBase + c * 4);
        }
    };

    stage(0, 0);        cp_commit();
    stage(1, GBK);      cp_commit();

    for (int t = 0; t < NKT; t++) {
        const int buf = t % 3;
        if (t + 1 < NKT) cp_wait<1>(); else cp_wait<0>();
        __syncthreads();

        const float* As = sm + buf * STAGE_FL;
        const float* Bs = As + STAGE_A;
#pragma unroll
        for (int kk = 0; kk < GBK; kk += 8) {
            wmma::fragment<wmma::matrix_a, 16, 16, 8, wmma::precision::tf32, wmma::row_major> af[4];
            wmma::fragment<wmma::matrix_b, 16, 16, 8, wmma::precision::tf32, wmma::row_major> bf[4];
#pragma unroll
            for (int i = 0; i < 4; i++)
                wmma::load_matrix_sync(af[i], &As[(wy * 64 + i * 16) * LDA + kk], LDA);
#pragma unroll
            for (int j = 0; j < 4; j++)
                wmma::load_matrix_sync(bf[j], &Bs[kk * LDB + wx * 64 + j * 16], LDB);
#pragma unroll
            for (int i = 0; i < 4; i++)
#pragma unroll
                for (int j = 0; j < 4; j++)
                    wmma::mma_sync(acc[i][j], af[i], bf[j], acc[i][j]);
        }

        if (t + 2 < NKT) { stage((t + 2) % 3, (t + 2) * GBK); cp_commit(); }
    }
    __syncthreads();

    // epilogue in two N-halves of 128 cols via smem staging
    float* Cs = sm;  // [128][132]
#pragma unroll
    for (int half = 0; half < 2; half++) {
        if ((wx >> 1) == half) {
#pragma unroll
            for (int i = 0; i < 4; i++)
#pragma unroll
                for (int j = 0; j < 4; j++)
                    wmma::store_matrix_sync(&Cs[(wy * 64 + i * 16) * LDC + (wx & 1) * 64 + j * 16],
                                            acc[i][j], LDC, wmma::mem_row_major);
        }
        __syncthreads();
#pragma unroll
        for (int it = 0; it < 16; it++) {
            int idx = tid + it * 256;           // float4 index, 4096 total
            int row = idx >> 5, c = idx & 31;
            float4 v = *(float4*)&Cs[row * LDC + c * 4];
            int col = nBase + half * 128 + c * 4;
            float4 bi = *(const float4*)(bias + col);
            v.x += bi.x; v.y += bi.y; v.z += bi.z; v.w += bi.w;
            *(float4*)(C + (size_t)(mBase + row) * D_DIM + col) = v;
        }
        __syncthreads();
    }
}

// ---------------- RoPE in-place on q and k ----------------
__global__ __launch_bounds__(256) void rope_kernel(float* __restrict__ q,
                                                   float* __restrict__ k,
                                                   const int* __restrict__ positions) {
    int idx = blockIdx.x * blockDim.x + threadIdx.x;
    const int total = B_SZ * S_LEN * NH * 64;
    if (idx >= total) return;
    int j = idx & 63;
    int t = idx >> 6;
    int h = t % NH; t /= NH;
    int s = t % S_LEN;
    int b = t / S_LEN;

    double e = (double)(2 * j) * (1.0 / 128.0);
    double invf = exp(-e * 13.122363377404328);  // ln(500000)
    double f = (double)positions[s] * invf;
    float c = (float)cos(f);
    float sn = (float)sin(f);

    size_t base = ((size_t)(b * S_LEN + s)) * D_DIM + (size_t)h * HD;
    float a = q[base + j], bb = q[base + 64 + j];
    q[base + j]      = a * c - bb * sn;
    q[base + 64 + j] = bb * c + a * sn;
    a = k[base + j]; bb = k[base + 64 + j];
    k[base + j]      = a * c - bb * sn;
    k[base + 64 + j] = bb * c + a * sn;
}

// ---------------- lambda per head ----------------
__global__ __launch_bounds__(256) void lam_kernel(const float* __restrict__ lq1,
                                                  const float* __restrict__ lk1,
                                                  const float* __restrict__ lq2,
                                                  const float* __restrict__ lk2,
                                                  const float* __restrict__ lam_init) {
    int h = threadIdx.x >> 5;
    int lane = threadIdx.x & 31;
    float s1 = 0.f, s2 = 0.f;
#pragma unroll
    for (int d = lane; d < HD; d += 32) {
        s1 = fmaf(lq1[h * HD + d], lk1[h * HD + d], s1);
        s2 = fmaf(lq2[h * HD + d], lk2[h * HD + d], s2);
    }
#pragma unroll
    for (int off = 16; off; off >>= 1) {
        s1 += __shfl_xor_sync(0xffffffffu, s1, off);
        s2 += __shfl_xor_sync(0xffffffffu, s2, off);
    }
    if (lane == 0 && h < HALF_H) {
        float l = expf(s1) - expf(s2) + lam_init[h];
        g_lam[h] = fminf(fmaxf(l, 0.f), 1.f);
    }
}

// ---------------- flash attention (causal, fp32) ----------------
#define FM 64
#define FN 64
#define FLASH_SMEM ((2 * 128 * 65 + 64 * 128 + 64 * 65 + 3 * 64) * 4)

__global__ __launch_bounds__(256) void flash_kernel(const float* __restrict__ Q,
                                                    const float* __restrict__ K,
                                                    const float* __restrict__ V,
                                                    float* __restrict__ O) {
    extern __shared__ float sm[];
    float* Qt = sm;                    // [128][65]  Qt[kk][m]
    float* Kt = Qt + 128 * 65;         // [128][65]  Kt[kk][n]
    float* Vs = Kt + 128 * 65;         // [64][128]
    float* Ps = Vs + 64 * 128;         // [64][65]
    float* mi = Ps + 64 * 65;          // [64]
    float* li = mi + 64;               // [64]
    float* al = li + 64;               // [64]

    const int qBase = blockIdx.x * FM;
    const int h = blockIdx.y;
    const int b = blockIdx.z;
    const int tid = threadIdx.x;
    const int ty = tid / 16, tx = tid % 16;
    const size_t headOff = (size_t)h * HD;
    const float scale = 0.088388347648318447f;  // 1/sqrt(128)

    for (int s4 = tid; s4 < FM * (HD / 4); s4 += 256) {
        int row = s4 >> 5;
        int c4 = s4 & 31;
        float4 v = *(const float4*)(Q + ((size_t)(b * S_LEN + qBase + row)) * D_DIM + headOff + c4 * 4);
        Qt[(c4 * 4 + 0) * 65 + row] = v.x;
        Qt[(c4 * 4 + 1) * 65 + row] = v.y;
        Qt[(c4 * 4 + 2) * 65 + row] = v.z;
        Qt[(c4 * 4 + 3) * 65 + row] = v.w;
    }
    if (tid < FM) { mi[tid] = -1e30f; li[tid] = 0.f; }

    float Oacc[4][8];
#pragma unroll
    for (int i = 0; i < 4; i++)
#pragma unroll
        for (int dd = 0; dd < 8; dd++) Oacc[i][dd] = 0.f;

    __syncthreads();

    for (int n0 = 0; n0 <= qBase; n0 += FN) {
        for (int s4 = tid; s4 < FN * (HD / 4); s4 += 256) {
            int row = s4 >> 5;
            int c4 = s4 & 31;
            size_t gb = ((size_t)(b * S_LEN + n0 + row)) * D_DIM + headOff + c4 * 4;
            float4 kv = *(const float4*)(K + gb);
            Kt[(c4 * 4 + 0) * 65 + row] = kv.x;
            Kt[(c4 * 4 + 1) * 65 + row] = kv.y;
            Kt[(c4 * 4 + 2) * 65 + row] = kv.z;
            Kt[(c4 * 4 + 3) * 65 + row] = kv.w;
            *(float4*)&Vs[row * HD + c4 * 4] = *(const float4*)(V + gb);
        }
        __syncthreads();

        float sc[4][4] = {};
#pragma unroll 4
        for (int kk = 0; kk < HD; kk++) {
            float rq[4], rk[4];
#pragma unroll
            for (int i = 0; i < 4; i++) rq[i] = Qt[kk * 65 + ty * 4 + i];
#pragma unroll
            for (int j = 0; j < 4; j++) rk[j] = Kt[kk * 65 + tx * 4 + j];
#pragma unroll
            for (int i = 0; i < 4; i++)
#pragma unroll
                for (int j = 0; j < 4; j++) sc[i][j] = fmaf(rq[i], rk[j], sc[i][j]);
        }
        bool diag = (n0 == qBase);
#pragma unroll
        for (int i = 0; i < 4; i++) {
            int m = ty * 4 + i;
#pragma unroll
            for (int j = 0; j < 4; j++) {
                int n = tx * 4 + j;
                float v = sc[i][j] * scale;
                if (diag && n > m) v = -1e30f;
                Ps[m * 65 + n] = v;
            }
        }
        __syncthreads();

        {
            int r = tid >> 2;
            int part = tid & 3;
            float lm = -1e30f;
#pragma unroll
            for (int n = part * 16; n < part * 16 + 16; n++) lm = fmaxf(lm, Ps[r * 65 + n]);
            lm = fmaxf(lm, __shfl_xor_sync(0xffffffffu, lm, 1));
            lm = fmaxf(lm, __shfl_xor_sync(0xffffffffu, lm, 2));
            float oldm = mi[r];
            float newm = fmaxf(oldm, lm);
            float lsum = 0.f;
#pragma unroll
            for (int n = part * 16; n < part * 16 + 16; n++) {
                float e = __expf(Ps[r * 65 + n] - newm);
                Ps[r * 65 + n] = e;
                lsum += e;
            }
            lsum += __shfl_xor_sync(0xffffffffu, lsum, 1);
            lsum += __shfl_xor_sync(0xffffffffu, lsum, 2);
            if (part == 0) {
                float alpha = __expf(oldm - newm);
                mi[r] = newm;
                li[r] = li[r] * alpha + lsum;
                al[r] = alpha;
            }
        }
        __syncthreads();

        float alr[4];
#pragma unroll
        for (int i = 0; i < 4; i++) alr[i] = al[ty * 4 + i];
#pragma unroll
        for (int i = 0; i < 4; i++)
#pragma unroll
            for (int dd = 0; dd < 8; dd++) Oacc[i][dd] *= alr[i];

        for (int n = 0; n < FN; n++) {
            float vv[8];
            *(float4*)&vv[0] = *(const float4*)&Vs[n * HD + tx * 8];
            *(float4*)&vv[4] = *(const float4*)&Vs[n * HD + tx * 8 + 4];
#pragma unroll
            for (int i = 0; i < 4; i++) {
                float p = Ps[(ty * 4 + i) * 65 + n];
#pragma unroll
                for (int dd = 0; dd < 8; dd++) Oacc[i][dd] = fmaf(p, vv[dd], Oacc[i][dd]);
            }
        }
        __syncthreads();
    }

#pragma unroll
    for (int i = 0; i < 4; i++) {
        int m = ty * 4 + i;
        float inv = 1.0f / li[m];
        float4 o0, o1;
        o0.x = Oacc[i][0] * inv; o0.y = Oacc[i][1] * inv;
        o0.z = Oacc[i][2] * inv; o0.w = Oacc[i][3] * inv;
        o1.x = Oacc[i][4] * inv; o1.y = Oacc[i][5] * inv;
        o1.z = Oacc[i][6] * inv; o1.w = Oacc[i][7] * inv;
        size_t base = ((size_t)(b * S_LEN + qBase + m)) * D_DIM + headOff + tx * 8;
        *(float4*)(O + base) = o0;
        *(float4*)(O + base + 4) = o1;
    }
}

// ---------------- diff combine + headwise LayerNorm (tf32-rounded out) ----------------
__global__ __launch_bounds__(128) void combine_kernel(const float* __restrict__ attn,
                                                      const float* __restrict__ gamma,
                                                      const float* __restrict__ beta,
                                                      float* __restrict__ ctx) {
    int blk = blockIdx.x;
    int h = blk & 7;
    int row = blk >> 3;
    int d = threadIdx.x;
    size_t base = (size_t)row * D_DIM;

    float a1 = attn[base + h * HD + d];
    float a2 = attn[base + (h + 8) * HD + d];
    float o = a1 - g_lam[h] * a2;

    __shared__ float red[4];
    __shared__ float smean, svar;

    float s = o;
#pragma unroll
    for (int off = 16; off; off >>= 1) s += __shfl_xor_sync(0xffffffffu, s, off);
    if ((d & 31) == 0) red[d >> 5] = s;
    __syncthreads();
    if (d == 0) smean = (red[0] + red[1] + red[2] + red[3]) * (1.0f / 128.0f);
    __syncthreads();
    float mean = smean;
    float dv = o - mean;
    float s2 = dv * dv;
#pragma unroll
    for (int off = 16; off; off >>= 1) s2 += __shfl_xor_sync(0xffffffffu, s2, off);
    __syncthreads();
    if ((d & 31) == 0) red[d >> 5] = s2;
    __syncthreads();
    if (d == 0) svar = (red[0] + red[1] + red[2] + red[3]) * (1.0f / 128.0f);
    __syncthreads();

    float y = dv * rsqrtf(svar + EPS_HN);
    ctx[base + h * HD + d]       = wmma::__float_to_tf32(gamma[h] * y + beta[h]);
    ctx[base + (h + 8) * HD + d] = wmma::__float_to_tf32(gamma[h + 8] * y + beta[h + 8]);
}

// ---------------- launch ----------------
extern "C" void kernel_launch(void* const* d_in, const int* in_sizes, int n_in,
                              void* d_out, int out_size) {
    const float* x         = (const float*)d_in[0];
    const int*   positions = (const int*)  d_in[1];
    const float* wq        = (const float*)d_in[2];
    const float* bq        = (const float*)d_in[3];
    const float* wk        = (const float*)d_in[4];
    const float* bk        = (const float*)d_in[5];
    const float* wv        = (const float*)d_in[6];
    const float* bv        = (const float*)d_in[7];
    const float* wo        = (const float*)d_in[8];
    const float* bo        = (const float*)d_in[9];
    const float* g         = (const float*)d_in[10];
    const float* gamma     = (const float*)d_in[11];
    const float* beta      = (const float*)d_in[12];
    const float* lam_init  = (const float*)d_in[13];
    const float* lq1       = (const float*)d_in[14];
    const float* lk1       = (const float*)d_in[15];
    const float* lq2       = (const float*)d_in[16];
    const float* lk2       = (const float*)d_in[17];
    float* out = (float*)d_out;

    float *p_xn, *p_q, *p_k, *p_v, *p_attn, *p_ctx, *p_wr;
    cudaGetSymbolAddress((void**)&p_xn,   g_xn);
    cudaGetSymbolAddress((void**)&p_q,    g_q);
    cudaGetSymbolAddress((void**)&p_k,    g_k);
    cudaGetSymbolAddress((void**)&p_v,    g_v);
    cudaGetSymbolAddress((void**)&p_attn, g_attn);
    cudaGetSymbolAddress((void**)&p_ctx,  g_ctx);
    cudaGetSymbolAddress((void**)&p_wr,   g_wr);

    const int M = B_SZ * S_LEN;   // 4096

    // tf32-round all four weight matrices (z = 0..3 -> wq,wk,wv,wo)
    dim3 rwGrid(D_DIM * D_DIM / (256 * 4), 4);
    round_w_kernel<<<rwGrid, 256>>>(wq, wk, wv, wo, p_wr);

    rmsnorm_kernel<<<M, 256>>>(x, g, p_xn);

    cudaFuncSetAttribute(gemm_tf32, cudaFuncAttributeMaxDynamicSharedMemorySize, GEMM_SMEM);
    // fused Q,K,V projections: blockIdx.z selects weight slice / bias / output
    dim3 qkvGrid(D_DIM / CTA_N, M / CTA_M, 3);
    gemm_tf32<<<qkvGrid, 256, GEMM_SMEM>>>(p_xn, p_wr, 0, bq, bk, bv, p_q, p_k, p_v);

    const int ropeTotal = B_SZ * S_LEN * NH * 64;
    rope_kernel<<<(ropeTotal + 255) / 256, 256>>>(p_q, p_k, positions);

    lam_kernel<<<1, 256>>>(lq1, lk1, lq2, lk2, lam_init);

    cudaFuncSetAttribute(flash_kernel, cudaFuncAttributeMaxDynamicSharedMemorySize, FLASH_SMEM);
    dim3 flashGrid(S_LEN / FM, NH, B_SZ);
    flash_kernel<<<flashGrid, 256, FLASH_SMEM>>>(p_q, p_k, p_v, p_attn);

    combine_kernel<<<M * HALF_H, 128>>>(p_attn, gamma, beta, p_ctx);

    dim3 oGrid(D_DIM / CTA_N, M / CTA_M, 1);
    gemm_tf32<<<oGrid, 256, GEMM_SMEM>>>(p_ctx, p_wr, 3, bo, bo, bo, out, out, out);
}

// round 6
// speedup vs baseline: 1.8474x; 1.3196x over previous
#include <cuda_runtime.h>
#include <cuda_bf16.h>
#include <math.h>
#include <mma.h>
#include <cstdint>

using namespace nvcuda;

#define B_SZ 2
#define S_LEN 2048
#define D_DIM 2048
#define NH 16
#define HD 128
#define HALF_H 8
#define EPS_RMS 1e-6f
#define EPS_HN 1e-5f

// ---------------- scratch (no allocations allowed) ----------------
__device__ float g_xn[B_SZ * S_LEN * D_DIM];
__device__ float g_q [B_SZ * S_LEN * D_DIM];
__device__ float g_k [B_SZ * S_LEN * D_DIM];
__device__ float g_v [B_SZ * S_LEN * D_DIM];
__device__ float g_attn[B_SZ * S_LEN * D_DIM];
__device__ float g_ctx [B_SZ * S_LEN * D_DIM];
__device__ float g_wr  [4 * D_DIM * D_DIM];   // tf32-rounded weights [K,N], 4 slices
__device__ float g_rope[2 * S_LEN * 64];      // cos | sin tables
__device__ float g_lam[HALF_H];

// ---------------- helpers ----------------
__device__ __forceinline__ uint32_t smem_u32(const void* p) {
    uint32_t a;
    asm("{ .reg .u64 t; cvta.to.shared.u64 t, %1; cvt.u32.u64 %0, t; }" : "=r"(a) : "l"(p));
    return a;
}
__device__ __forceinline__ void cp_async16(uint32_t dst, const void* src) {
    asm volatile("cp.async.cg.shared.global [%0], [%1], 16;" :: "r"(dst), "l"(src));
}
__device__ __forceinline__ void cp_commit() {
    asm volatile("cp.async.commit_group;");
}
template<int N> __device__ __forceinline__ void cp_wait() {
    asm volatile("cp.async.wait_group %0;" :: "n"(N));
}

// ---------------- tf32 rounding of weights ----------------
__global__ __launch_bounds__(256) void round_w_kernel(const float* __restrict__ w0,
                                                      const float* __restrict__ w1,
                                                      const float* __restrict__ w2,
                                                      const float* __restrict__ w3,
                                                      float* __restrict__ dst) {
    const int z = blockIdx.y;
    const float* src = (z == 0) ? w0 : (z == 1) ? w1 : (z == 2) ? w2 : w3;
    float* d = dst + (size_t)z * D_DIM * D_DIM;
    int i4 = blockIdx.x * 256 + threadIdx.x;
    float4 v = *(const float4*)(src + (size_t)i4 * 4);
    v.x = wmma::__float_to_tf32(v.x); v.y = wmma::__float_to_tf32(v.y);
    v.z = wmma::__float_to_tf32(v.z); v.w = wmma::__float_to_tf32(v.w);
    *(float4*)(d + (size_t)i4 * 4) = v;
}

// ---------------- RMSNorm (emits tf32-rounded output) ----------------
__global__ __launch_bounds__(256) void rmsnorm_kernel(const float* __restrict__ x,
                                                      const float* __restrict__ g,
                                                      float* __restrict__ out) {
    int row = blockIdx.x;
    const float* xr = x + (size_t)row * D_DIM;
    float* orow = out + (size_t)row * D_DIM;
    float s = 0.f;
#pragma unroll
    for (int it = 0; it < D_DIM / 256; it++) {
        float v = (xr[threadIdx.x + it * 256] + EPS_RMS) + EPS_RMS;
        s = fmaf(v, v, s);
    }
#pragma unroll
    for (int off = 16; off; off >>= 1) s += __shfl_xor_sync(0xffffffffu, s, off);
    __shared__ float red[8];
    __shared__ float sinv;
    if ((threadIdx.x & 31) == 0) red[threadIdx.x >> 5] = s;
    __syncthreads();
    if (threadIdx.x == 0) {
        float t = 0.f;
#pragma unroll
        for (int i = 0; i < 8; i++) t += red[i];
        float n = sqrtf(t) * 45.254833995939045f;  // sqrt(2048)
        sinv = 1.0f / (n + EPS_RMS);
    }
    __syncthreads();
    float inv = sinv;
#pragma unroll
    for (int it = 0; it < D_DIM / 256; it++) {
        int d = threadIdx.x + it * 256;
        orow[d] = wmma::__float_to_tf32((xr[d] + EPS_RMS) * inv * g[d]);
    }
}

// ---------------- TF32 WMMA GEMM, cp.async 3-stage pipeline ----------------
#define CTA_M 128
#define CTA_N 256
#define GBK 32
#define LDA 36
#define LDB 260
#define LDC 132
#define STAGE_A (CTA_M * LDA)
#define STAGE_B (GBK * LDB)
#define STAGE_FL (STAGE_A + STAGE_B)
#define NSTAGE 3
#define GEMM_SMEM (NSTAGE * STAGE_FL * 4)
#define NKT (D_DIM / GBK)

__global__ __launch_bounds__(256) void gemm_tf32(const float* __restrict__ A,
                                                 const float* __restrict__ Wbase,
                                                 int zoff,
                                                 const float* __restrict__ b0,
                                                 const float* __restrict__ b1,
                                                 const float* __restrict__ b2,
                                                 float* __restrict__ C0,
                                                 float* __restrict__ C1,
                                                 float* __restrict__ C2) {
    extern __shared__ float sm[];
    const uint32_t smem_base = smem_u32(sm);
    const int z = blockIdx.z;
    const float* W    = Wbase + (size_t)(z + zoff) * D_DIM * D_DIM;
    const float* bias = (z == 0) ? b0 : (z == 1) ? b1 : b2;
    float* C          = (z == 0) ? C0 : (z == 1) ? C1 : C2;

    const int tid = threadIdx.x;
    const int warpId = tid >> 5;
    const int wy = warpId >> 2;
    const int wx = warpId & 3;
    const int mBase = blockIdx.y * CTA_M;
    const int nBase = blockIdx.x * CTA_N;

    wmma::fragment<wmma::accumulator, 16, 16, 8, float> acc[4][4];
#pragma unroll
    for (int i = 0; i < 4; i++)
#pragma unroll
        for (int j = 0; j < 4; j++) wmma::fill_fragment(acc[i][j], 0.0f);

    auto stage = [&](int buf, int k0) {
        uint32_t sa = smem_base + (uint32_t)(buf * STAGE_FL * 4);
        uint32_t sb = sa + STAGE_A * 4;
#pragma unroll
        for (int it = 0; it < 4; it++) {
            int idx = tid + it * 256;
            int row = idx >> 3, c = idx & 7;
            cp_async16(sa + (uint32_t)(row * LDA + c * 4) * 4,
                       A + (size_t)(mBase + row) * D_DIM + k0 + c * 4);
        }
#pragma unroll
        for (int it = 0; it < 8; it++) {
            int idx = tid + it * 256;
            int row = idx >> 6, c = idx & 63;
            cp_async16(sb + (uint32_t)(row * LDB + c * 4) * 4,
                       W + (size_t)(k0 + row) * D_DIM + nBase + c * 4);
        }
    };

    stage(0, 0);        cp_commit();
    stage(1, GBK);      cp_commit();

    for (int t = 0; t < NKT; t++) {
        const int buf = t % 3;
        if (t + 1 < NKT) cp_wait<1>(); else cp_wait<0>();
        __syncthreads();

        const float* As = sm + buf * STAGE_FL;
        const float* Bs = As + STAGE_A;
#pragma unroll
        for (int kk = 0; kk < GBK; kk += 8) {
            wmma::fragment<wmma::matrix_a, 16, 16, 8, wmma::precision::tf32, wmma::row_major> af[4];
            wmma::fragment<wmma::matrix_b, 16, 16, 8, wmma::precision::tf32, wmma::row_major> bf[4];
#pragma unroll
            for (int i = 0; i < 4; i++)
                wmma::load_matrix_sync(af[i], &As[(wy * 64 + i * 16) * LDA + kk], LDA);
#pragma unroll
            for (int j = 0; j < 4; j++)
                wmma::load_matrix_sync(bf[j], &Bs[kk * LDB + wx * 64 + j * 16], LDB);
#pragma unroll
            for (int i = 0; i < 4; i++)
#pragma unroll
                for (int j = 0; j < 4; j++)
                    wmma::mma_sync(acc[i][j], af[i], bf[j], acc[i][j]);
        }

        if (t + 2 < NKT) { stage((t + 2) % 3, (t + 2) * GBK); cp_commit(); }
    }
    __syncthreads();

    float* Cs = sm;
#pragma unroll
    for (int half = 0; half < 2; half++) {
        if ((wx >> 1) == half) {
#pragma unroll
            for (int i = 0; i < 4; i++)
#pragma unroll
                for (int j = 0; j < 4; j++)
                    wmma::store_matrix_sync(&Cs[(wy * 64 + i * 16) * LDC + (wx & 1) * 64 + j * 16],
                                            acc[i][j], LDC, wmma::mem_row_major);
        }
        __syncthreads();
#pragma unroll
        for (int it = 0; it < 16; it++) {
            int idx = tid + it * 256;
            int row = idx >> 5, c = idx & 31;
            float4 v = *(float4*)&Cs[row * LDC + c * 4];
            int col = nBase + half * 128 + c * 4;
            float4 bi = *(const float4*)(bias + col);
            v.x += bi.x; v.y += bi.y; v.z += bi.z; v.w += bi.w;
            *(float4*)(C + (size_t)(mBase + row) * D_DIM + col) = v;
        }
        __syncthreads();
    }
}

// ---------------- RoPE: fp64 table (once) + fast fp32 apply ----------------
__global__ __launch_bounds__(256) void rope_table_kernel(const int* __restrict__ positions) {
    int idx = blockIdx.x * 256 + threadIdx.x;      // S_LEN*64
    int j = idx & 63;
    int s = idx >> 6;
    double e = (double)(2 * j) * (1.0 / 128.0);
    double invf = exp(-e * 13.122363377404328);    // ln(500000)
    double f = (double)positions[s] * invf;
    g_rope[idx] = (float)cos(f);
    g_rope[S_LEN * 64 + idx] = (float)sin(f);
}

__global__ __launch_bounds__(256) void rope_apply_kernel(float* __restrict__ q,
                                                         float* __restrict__ k) {
    int idx = blockIdx.x * blockDim.x + threadIdx.x;
    const int total = B_SZ * S_LEN * NH * 64;
    if (idx >= total) return;
    int j = idx & 63;
    int t = idx >> 6;
    int h = t % NH; t /= NH;
    int s = t % S_LEN;
    int b = t / S_LEN;

    float c  = g_rope[s * 64 + j];
    float sn = g_rope[S_LEN * 64 + s * 64 + j];

    size_t base = ((size_t)(b * S_LEN + s)) * D_DIM + (size_t)h * HD;
    float a = q[base + j], bb = q[base + 64 + j];
    q[base + j]      = a * c - bb * sn;
    q[base + 64 + j] = bb * c + a * sn;
    a = k[base + j]; bb = k[base + 64 + j];
    k[base + j]      = a * c - bb * sn;
    k[base + 64 + j] = bb * c + a * sn;
}

// ---------------- lambda per head ----------------
__global__ __launch_bounds__(256) void lam_kernel(const float* __restrict__ lq1,
                                                  const float* __restrict__ lk1,
                                                  const float* __restrict__ lq2,
                                                  const float* __restrict__ lk2,
                                                  const float* __restrict__ lam_init) {
    int h = threadIdx.x >> 5;
    int lane = threadIdx.x & 31;
    float s1 = 0.f, s2 = 0.f;
#pragma unroll
    for (int d = lane; d < HD; d += 32) {
        s1 = fmaf(lq1[h * HD + d], lk1[h * HD + d], s1);
        s2 = fmaf(lq2[h * HD + d], lk2[h * HD + d], s2);
    }
#pragma unroll
    for (int off = 16; off; off >>= 1) {
        s1 += __shfl_xor_sync(0xffffffffu, s1, off);
        s2 += __shfl_xor_sync(0xffffffffu, s2, off);
    }
    if (lane == 0 && h < HALF_H) {
        float l = expf(s1) - expf(s2) + lam_init[h];
        g_lam[h] = fminf(fmaxf(l, 0.f), 1.f);
    }
}

// ---------------- WMMA flash attention (causal, tf32 tensor cores) ----------------
#define FM 64
#define FN 64
#define FLDQ 132
#define FLDP 72
// layout: Qs Ks Vs Us Os (each 64*132) then Ps (64*72), mi/li/al (64 each)
#define F_QS 0
#define F_KS (64 * FLDQ)
#define F_VS (2 * 64 * FLDQ)
#define F_US (3 * 64 * FLDQ)
#define F_OS (4 * 64 * FLDQ)
#define F_PS (5 * 64 * FLDQ)
#define F_MI (F_PS + 64 * FLDP)
#define F_LI (F_MI + 64)
#define F_AL (F_LI + 64)
#define FLASH_SMEM ((F_AL + 64) * 4)

__global__ __launch_bounds__(256) void flash_wmma(const float* __restrict__ Q,
                                                  const float* __restrict__ K,
                                                  const float* __restrict__ V,
                                                  float* __restrict__ O) {
    extern __shared__ float sm[];
    float* Qs = sm + F_QS;
    float* Ks = sm + F_KS;
    float* Vs = sm + F_VS;
    float* Us = sm + F_US;
    float* Os = sm + F_OS;
    float* Ps = sm + F_PS;
    float* mi = sm + F_MI;
    float* li = sm + F_LI;
    float* al = sm + F_AL;

    // heavy (large qBase) blocks first for better tail behavior
    const int qBase = (gridDim.x - 1 - blockIdx.x) * FM;
    const int h = blockIdx.y;
    const int b = blockIdx.z;
    const int tid = threadIdx.x;
    const int warp = tid >> 5;
    const size_t headOff = (size_t)h * HD;
    const float scale = 0.088388347648318447f;  // 1/sqrt(128)

    // load Q tile (rounded to tf32), zero O, init stats
    for (int idx = tid; idx < FM * 32; idx += 256) {
        int row = idx >> 5, c4 = idx & 31;
        float4 v = *(const float4*)(Q + ((size_t)(b * S_LEN + qBase + row)) * D_DIM + headOff + c4 * 4);
        v.x = wmma::__float_to_tf32(v.x); v.y = wmma::__float_to_tf32(v.y);
        v.z = wmma::__float_to_tf32(v.z); v.w = wmma::__float_to_tf32(v.w);
        *(float4*)&Qs[row * FLDQ + c4 * 4] = v;
        *(float4*)&Os[row * FLDQ + c4 * 4] = make_float4(0.f, 0.f, 0.f, 0.f);
    }
    if (tid < FM) { mi[tid] = -1e30f; li[tid] = 0.f; }
    __syncthreads();

    for (int n0 = 0; n0 <= qBase; n0 += FN) {
        // stage K (rounded) and V (rounded)
        for (int idx = tid; idx < FN * 32; idx += 256) {
            int row = idx >> 5, c4 = idx & 31;
            size_t gb = ((size_t)(b * S_LEN + n0 + row)) * D_DIM + headOff + c4 * 4;
            float4 kv = *(const float4*)(K + gb);
            kv.x = wmma::__float_to_tf32(kv.x); kv.y = wmma::__float_to_tf32(kv.y);
            kv.z = wmma::__float_to_tf32(kv.z); kv.w = wmma::__float_to_tf32(kv.w);
            *(float4*)&Ks[row * FLDQ + c4 * 4] = kv;
            float4 vv = *(const float4*)(V + gb);
            vv.x = wmma::__float_to_tf32(vv.x); vv.y = wmma::__float_to_tf32(vv.y);
            vv.z = wmma::__float_to_tf32(vv.z); vv.w = wmma::__float_to_tf32(vv.w);
            *(float4*)&Vs[row * FLDQ + c4 * 4] = vv;
        }
        __syncthreads();

        // ---- S = Q @ K^T : warp (wy,wx) handles rows wy*16, cols wx*32
        {
            const int wy = warp >> 1, wx = warp & 1;
            wmma::fragment<wmma::accumulator, 16, 16, 8, float> sacc[2];
            wmma::fill_fragment(sacc[0], 0.f);
            wmma::fill_fragment(sacc[1], 0.f);
#pragma unroll
            for (int k = 0; k < HD; k += 8) {
                wmma::fragment<wmma::matrix_a, 16, 16, 8, wmma::precision::tf32, wmma::row_major> af;
                wmma::load_matrix_sync(af, &Qs[(wy * 16) * FLDQ + k], FLDQ);
#pragma unroll
                for (int j = 0; j < 2; j++) {
                    wmma::fragment<wmma::matrix_b, 16, 16, 8, wmma::precision::tf32, wmma::col_major> bf;
                    wmma::load_matrix_sync(bf, &Ks[(wx * 32 + j * 16) * FLDQ + k], FLDQ);
                    wmma::mma_sync(sacc[j], af, bf, sacc[j]);
                }
            }
#pragma unroll
            for (int j = 0; j < 2; j++)
                wmma::store_matrix_sync(&Ps[(wy * 16) * FLDP + wx * 32 + j * 16],
                                        sacc[j], FLDP, wmma::mem_row_major);
        }
        __syncthreads();

        // ---- online softmax (scalar, 4 threads per row)
        {
            int r = tid >> 2;
            int part = tid & 3;
            float* Prow = Ps + r * FLDP;
            bool diag = (n0 == qBase);
            float lm = -1e30f;
#pragma unroll
            for (int n = part * 16; n < part * 16 + 16; n++) {
                float v = Prow[n] * scale;
                if (diag && n > r) v = -1e30f;
                Prow[n] = v;
                lm = fmaxf(lm, v);
            }
            lm = fmaxf(lm, __shfl_xor_sync(0xffffffffu, lm, 1));
            lm = fmaxf(lm, __shfl_xor_sync(0xffffffffu, lm, 2));
            float oldm = mi[r];
            float newm = fmaxf(oldm, lm);
            float lsum = 0.f;
#pragma unroll
            for (int n = part * 16; n < part * 16 + 16; n++) {
                float e = __expf(Prow[n] - newm);
                Prow[n] = wmma::__float_to_tf32(e);
                lsum += e;
            }
            lsum += __shfl_xor_sync(0xffffffffu, lsum, 1);
            lsum += __shfl_xor_sync(0xffffffffu, lsum, 2);
            if (part == 0) {
                float alpha = __expf(oldm - newm);
                mi[r] = newm;
                li[r] = li[r] * alpha + lsum;
                al[r] = alpha;
            }
        }
        __syncthreads();

        // ---- U = P @ V : warp (wy,wx) rows wy*16, cols wx*64 (4 frags)
        {
            const int wy = warp >> 1, wx = warp & 1;
            wmma::fragment<wmma::accumulator, 16, 16, 8, float> oacc[4];
#pragma unroll
            for (int j = 0; j < 4; j++) wmma::fill_fragment(oacc[j], 0.f);
#pragma unroll
            for (int k = 0; k < FN; k += 8) {
                wmma::fragment<wmma::matrix_a, 16, 16, 8, wmma::precision::tf32, wmma::row_major> af;
                wmma::load_matrix_sync(af, &Ps[(wy * 16) * FLDP + k], FLDP);
#pragma unroll
                for (int j = 0; j < 4; j++) {
                    wmma::fragment<wmma::matrix_b, 16, 16, 8, wmma::precision::tf32, wmma::row_major> bf;
                    wmma::load_matrix_sync(bf, &Vs[k * FLDQ + wx * 64 + j * 16], FLDQ);
                    wmma::mma_sync(oacc[j], af, bf, oacc[j]);
                }
            }
#pragma unroll
            for (int j = 0; j < 4; j++)
                wmma::store_matrix_sync(&Us[(wy * 16) * FLDQ + wx * 64 + j * 16],
                                        oacc[j], FLDQ, wmma::mem_row_major);
        }
        __syncthreads();

        // ---- O = O*alpha + U
        for (int idx = tid; idx < FM * 32; idx += 256) {
            int row = idx >> 5, c4 = idx & 31;
            float a = al[row];
            float4 o = *(float4*)&Os[row * FLDQ + c4 * 4];
            float4 u = *(float4*)&Us[row * FLDQ + c4 * 4];
            o.x = fmaf(o.x, a, u.x); o.y = fmaf(o.y, a, u.y);
            o.z = fmaf(o.z, a, u.z); o.w = fmaf(o.w, a, u.w);
            *(float4*)&Os[row * FLDQ + c4 * 4] = o;
        }
        __syncthreads();
    }

    // epilogue: normalize, store
    for (int idx = tid; idx < FM * 32; idx += 256) {
        int row = idx >> 5, c4 = idx & 31;
        float inv = 1.0f / li[row];
        float4 o = *(float4*)&Os[row * FLDQ + c4 * 4];
        o.x *= inv; o.y *= inv; o.z *= inv; o.w *= inv;
        *(float4*)(O + ((size_t)(b * S_LEN + qBase + row)) * D_DIM + headOff + c4 * 4) = o;
    }
}

// ---------------- diff combine + headwise LayerNorm (tf32-rounded out) ----------------
__global__ __launch_bounds__(128) void combine_kernel(const float* __restrict__ attn,
                                                      const float* __restrict__ gamma,
                                                      const float* __restrict__ beta,
                                                      float* __restrict__ ctx) {
    int blk = blockIdx.x;
    int h = blk & 7;
    int row = blk >> 3;
    int d = threadIdx.x;
    size_t base = (size_t)row * D_DIM;

    float a1 = attn[base + h * HD + d];
    float a2 = attn[base + (h + 8) * HD + d];
    float o = a1 - g_lam[h] * a2;

    __shared__ float red[4];
    __shared__ float smean, svar;

    float s = o;
#pragma unroll
    for (int off = 16; off; off >>= 1) s += __shfl_xor_sync(0xffffffffu, s, off);
    if ((d & 31) == 0) red[d >> 5] = s;
    __syncthreads();
    if (d == 0) smean = (red[0] + red[1] + red[2] + red[3]) * (1.0f / 128.0f);
    __syncthreads();
    float mean = smean;
    float dv = o - mean;
    float s2 = dv * dv;
#pragma unroll
    for (int off = 16; off; off >>= 1) s2 += __shfl_xor_sync(0xffffffffu, s2, off);
    __syncthreads();
    if ((d & 31) == 0) red[d >> 5] = s2;
    __syncthreads();
    if (d == 0) svar = (red[0] + red[1] + red[2] + red[3]) * (1.0f / 128.0f);
    __syncthreads();

    float y = dv * rsqrtf(svar + EPS_HN);
    ctx[base + h * HD + d]       = wmma::__float_to_tf32(gamma[h] * y + beta[h]);
    ctx[base + (h + 8) * HD + d] = wmma::__float_to_tf32(gamma[h + 8] * y + beta[h + 8]);
}

// ---------------- launch ----------------
extern "C" void kernel_launch(void* const* d_in, const int* in_sizes, int n_in,
                              void* d_out, int out_size) {
    const float* x         = (const float*)d_in[0];
    const int*   positions = (const int*)  d_in[1];
    const float* wq        = (const float*)d_in[2];
    const float* bq        = (const float*)d_in[3];
    const float* wk        = (const float*)d_in[4];
    const float* bk        = (const float*)d_in[5];
    const float* wv        = (const float*)d_in[6];
    const float* bv        = (const float*)d_in[7];
    const float* wo        = (const float*)d_in[8];
    const float* bo        = (const float*)d_in[9];
    const float* g         = (const float*)d_in[10];
    const float* gamma     = (const float*)d_in[11];
    const float* beta      = (const float*)d_in[12];
    const float* lam_init  = (const float*)d_in[13];
    const float* lq1       = (const float*)d_in[14];
    const float* lk1       = (const float*)d_in[15];
    const float* lq2       = (const float*)d_in[16];
    const float* lk2       = (const float*)d_in[17];
    float* out = (float*)d_out;

    float *p_xn, *p_q, *p_k, *p_v, *p_attn, *p_ctx, *p_wr;
    cudaGetSymbolAddress((void**)&p_xn,   g_xn);
    cudaGetSymbolAddress((void**)&p_q,    g_q);
    cudaGetSymbolAddress((void**)&p_k,    g_k);
    cudaGetSymbolAddress((void**)&p_v,    g_v);
    cudaGetSymbolAddress((void**)&p_attn, g_attn);
    cudaGetSymbolAddress((void**)&p_ctx,  g_ctx);
    cudaGetSymbolAddress((void**)&p_wr,   g_wr);

    const int M = B_SZ * S_LEN;   // 4096

    dim3 rwGrid(D_DIM * D_DIM / (256 * 4), 4);
    round_w_kernel<<<rwGrid, 256>>>(wq, wk, wv, wo, p_wr);

    rope_table_kernel<<<S_LEN * 64 / 256, 256>>>(positions);

    rmsnorm_kernel<<<M, 256>>>(x, g, p_xn);

    cudaFuncSetAttribute(gemm_tf32, cudaFuncAttributeMaxDynamicSharedMemorySize, GEMM_SMEM);
    dim3 qkvGrid(D_DIM / CTA_N, M / CTA_M, 3);
    gemm_tf32<<<qkvGrid, 256, GEMM_SMEM>>>(p_xn, p_wr, 0, bq, bk, bv, p_q, p_k, p_v);

    const int ropeTotal = B_SZ * S_LEN * NH * 64;
    rope_apply_kernel<<<(ropeTotal + 255) / 256, 256>>>(p_q, p_k);

    lam_kernel<<<1, 256>>>(lq1, lk1, lq2, lk2, lam_init);

    cudaFuncSetAttribute(flash_wmma, cudaFuncAttributeMaxDynamicSharedMemorySize, FLASH_SMEM);
    dim3 flashGrid(S_LEN / FM, NH, B_SZ);
    flash_wmma<<<flashGrid, 256, FLASH_SMEM>>>(p_q, p_k, p_v, p_attn);

    combine_kernel<<<M * HALF_H, 128>>>(p_attn, gamma, beta, p_ctx);

    dim3 oGrid(D_DIM / CTA_N, M / CTA_M, 1);
    gemm_tf32<<<oGrid, 256, GEMM_SMEM>>>(p_ctx, p_wr, 3, bo, bo, bo, out, out, out);
}